// round 12
// baseline (speedup 1.0000x reference)
#include <cuda_runtime.h>
#include <cuda_bf16.h>
#include <cstdint>
#include <math.h>

#define N_NODES 10000
#define F 256
#define E_POS 320000
#define E_TOT 330000
#define E_EVAL 100000
#define NEG_SLOPE 0.2f
#define EPS_F 1e-16f
#define SLOT_CAP 128

// ---------------- scratch (device globals; zero-initialized at load) ----------------
// g_deg / g_als* / g_ald* / g_bc rely on zero-init for the FIRST call and are
// re-zeroed at the tail of dot_kernel so every call sees identical state.
__device__ float g_bufA[N_NODES * F];     // gemm fp32 out
__device__ float g_bufB[N_NODES * F];     // aggregate2 out (final h)
__device__ float g_als1[N_NODES];
__device__ float g_ald1[N_NODES];
__device__ float g_als2[N_NODES];
__device__ float g_ald2[N_NODES];
__device__ float g_bc[F];                 // folded bias Win_b @ W1
__device__ int   g_deg[N_NODES];
__device__ int   g_srcs[N_NODES * SLOT_CAP];
__device__ __nv_bfloat16 g_Ah[N_NODES * F];      // node features split (A operand)
__device__ __nv_bfloat16 g_Al[N_NODES * F];
__device__ __nv_bfloat16 g_Xh[F * F];            // Win_W split, row-major [m][k]
__device__ __nv_bfloat16 g_Xl[F * F];
__device__ __nv_bfloat16 g_W1h[F * F];           // W1 split, transposed [n][k]
__device__ __nv_bfloat16 g_W1l[F * F];
__device__ __nv_bfloat16 g_Wh[2][F * F];         // 0: Wc (fold result), 1: W2 — [n][k]
__device__ __nv_bfloat16 g_Wl[2][F * F];

#define SW128(o) ((o) ^ (((o) >> 3) & 0x70))

__device__ __forceinline__ uint32_t smem_to_u32(const void* p) {
    uint32_t a;
    asm("{ .reg .u64 t; cvta.to.shared.u64 t, %1; cvt.u32.u64 %0, t; }"
        : "=r"(a) : "l"(p));
    return a;
}
__device__ __forceinline__ void ldsm_x4(uint32_t* r, uint32_t addr) {
    asm volatile("ldmatrix.sync.aligned.m8n8.x4.shared.b16 {%0,%1,%2,%3}, [%4];"
        : "=r"(r[0]), "=r"(r[1]), "=r"(r[2]), "=r"(r[3]) : "r"(addr));
}
__device__ __forceinline__ void mma16816(float* c, const uint32_t* a, const uint32_t* b) {
    asm volatile(
        "mma.sync.aligned.m16n8k16.row.col.f32.bf16.bf16.f32 "
        "{%0,%1,%2,%3}, {%4,%5,%6,%7}, {%8,%9}, {%0,%1,%2,%3};"
        : "+f"(c[0]), "+f"(c[1]), "+f"(c[2]), "+f"(c[3])
        : "r"(a[0]), "r"(a[1]), "r"(a[2]), "r"(a[3]), "r"(b[0]), "r"(b[1]));
}
__device__ __forceinline__ void cp_async16(uint32_t saddr, const void* g, bool valid) {
    int sz = valid ? 16 : 0;
    asm volatile("cp.async.cg.shared.global [%0], [%1], 16, %2;"
        :: "r"(saddr), "l"(g), "r"(sz) : "memory");
}
#define CP_COMMIT() asm volatile("cp.async.commit_group;" ::: "memory")
#define CP_WAIT(n)  asm volatile("cp.async.wait_group %0;" :: "n"(n) : "memory")

// ---------------- fused independent work: scatter + split + fold_bias ----------------
#define E_Q (E_TOT / 4)                          // 82500
#define SC_B ((E_Q + 255) / 256)                 // 323
#define M4_A (N_NODES * F / 4)                   // 640000
#define SP_B ((M4_A + 3 * F * F + 255) / 256)
#define FB_B (F / 32)                            // 8
#define WORK_B (SC_B + SP_B + FB_B)

__global__ void work_kernel(const int* __restrict__ pos_ei,
                            const float* __restrict__ x,
                            const float* __restrict__ WinW,
                            const float* __restrict__ W1,
                            const float* __restrict__ W2,
                            const float* __restrict__ Win_b) {
    int b = blockIdx.x;
    if (b < SC_B) {
        // ---- scatter (g_deg zero at call entry) ----
        int gid = b * blockDim.x + threadIdx.x;
        if (gid >= E_Q) return;
        #pragma unroll
        for (int q = 0; q < 4; q++) {
            int e = gid + q * E_Q;
            int src, dst;
            if (e < E_POS) { src = __ldg(pos_ei + e); dst = __ldg(pos_ei + E_POS + e); }
            else           { src = e - E_POS; dst = src; }
            int pos = atomicAdd(&g_deg[dst], 1);
            if (pos < SLOT_CAP) g_srcs[dst * SLOT_CAP + pos] = src;
        }
    } else if (b < SC_B + SP_B) {
        // ---- split x + Win_W + W1 + W2 ----
        int idx = (b - SC_B) * blockDim.x + threadIdx.x;
        if (idx < M4_A) {
            float4 v = reinterpret_cast<const float4*>(x)[idx];
            __nv_bfloat16 h0 = __float2bfloat16(v.x), h1 = __float2bfloat16(v.y);
            __nv_bfloat16 h2 = __float2bfloat16(v.z), h3 = __float2bfloat16(v.w);
            __nv_bfloat16 l0 = __float2bfloat16(v.x - __bfloat162float(h0));
            __nv_bfloat16 l1 = __float2bfloat16(v.y - __bfloat162float(h1));
            __nv_bfloat16 l2 = __float2bfloat16(v.z - __bfloat162float(h2));
            __nv_bfloat16 l3 = __float2bfloat16(v.w - __bfloat162float(h3));
            __nv_bfloat162* ph = reinterpret_cast<__nv_bfloat162*>(g_Ah);
            __nv_bfloat162* pl = reinterpret_cast<__nv_bfloat162*>(g_Al);
            ph[idx * 2]     = __nv_bfloat162(h0, h1);
            ph[idx * 2 + 1] = __nv_bfloat162(h2, h3);
            pl[idx * 2]     = __nv_bfloat162(l0, l1);
            pl[idx * 2 + 1] = __nv_bfloat162(l2, l3);
        } else {
            int i2 = idx - M4_A;
            if (i2 < 3 * F * F) {
                int w = i2 >> 16;
                int j = i2 & 65535;
                int k = j >> 8, n = j & 255;
                if (w == 0) {
                    float v = __ldg(WinW + j);
                    __nv_bfloat16 h = __float2bfloat16(v);
                    g_Xh[j] = h;
                    g_Xl[j] = __float2bfloat16(v - __bfloat162float(h));
                } else if (w == 1) {
                    float v = __ldg(W1 + j);
                    __nv_bfloat16 h = __float2bfloat16(v);
                    g_W1h[n * F + k] = h;
                    g_W1l[n * F + k] = __float2bfloat16(v - __bfloat162float(h));
                } else {
                    float v = __ldg(W2 + j);
                    __nv_bfloat16 h = __float2bfloat16(v);
                    g_Wh[1][n * F + k] = h;
                    g_Wl[1][n * F + k] = __float2bfloat16(v - __bfloat162float(h));
                }
            }
        }
    } else {
        // ---- fold_bias: bc += partials (g_bc zero at call entry) ----
        int n = threadIdx.x;
        int k0 = (b - SC_B - SP_B) * 32;
        float s = 0.f;
        #pragma unroll
        for (int kk = 0; kk < 32; kk++) {
            int k = k0 + kk;
            s = fmaf(__ldg(Win_b + k), __ldg(W1 + (size_t)k * F + n), s);
        }
        atomicAdd(&g_bc[n], s);
    }
}

// ---------------- pipelined HMMA GEMM ----------------
#define SA_H 0
#define SA_L 8192
#define SB_H 16384
#define SB_L 32768
#define STAGE_BYTES 49152
#define SMEM_MMA (2 * STAGE_BYTES + 1024)

__global__ __launch_bounds__(256, 2) void gemm_mma_kernel(
    const __nv_bfloat16* __restrict__ Ah, const __nv_bfloat16* __restrict__ Al,
    const __nv_bfloat16* __restrict__ Bh, const __nv_bfloat16* __restrict__ Bl,
    const float* __restrict__ bias,
    const float* __restrict__ a_src, const float* __restrict__ a_dst,
    float* __restrict__ als, float* __restrict__ ald,
    float* __restrict__ out, int write_split, int write_splitT, int M) {
    extern __shared__ char dsmem[];
    const int tid = threadIdx.x;
    const int wid = tid >> 5;
    const int lane = tid & 31;
    const int wm = wid >> 2;
    const int wn = wid & 3;
    const int row0 = blockIdx.y * 64;
    const int col0 = blockIdx.x * 128;

    uint32_t dsb = smem_to_u32(dsmem);
    uint32_t sb = (dsb + 1023) & ~1023u;

    float acc[2][4][4] = {};

    const int a_row = wm * 32 + (lane & 15);
    const int a_kb  = (lane >> 4) * 16;
    const int b_row = wn * 32 + (lane & 7) + ((lane >> 4) & 1) * 8;
    const int b_kb  = ((lane >> 3) & 1) * 16;

    const __nv_bfloat16* opsA[2] = { Ah, Al };
    const __nv_bfloat16* opsB[2] = { Bh, Bl };
    const int boffA[2] = { SA_H, SA_L };
    const int boffB[2] = { SB_H, SB_L };

    const int lr = tid >> 3;
    const int lj = tid & 7;

    #define LOAD_STAGE(cc, ss) do {                                              \
        uint32_t stb = sb + (ss) * STAGE_BYTES;                                   \
        _Pragma("unroll")                                                         \
        for (int t = 0; t < 2; t++) {                                             \
            _Pragma("unroll")                                                     \
            for (int it = 0; it < 2; it++) {                                      \
                int r = lr + it * 32;                                             \
                int grow = row0 + r;                                              \
                uint32_t off = SW128((uint32_t)(r * 128 + lj * 16));              \
                cp_async16(stb + boffA[t] + off,                                  \
                           opsA[t] + (size_t)grow * F + (cc) * 64 + lj * 8,       \
                           grow < M);                                             \
            }                                                                     \
        }                                                                         \
        _Pragma("unroll")                                                         \
        for (int t = 0; t < 2; t++) {                                             \
            _Pragma("unroll")                                                     \
            for (int it = 0; it < 4; it++) {                                      \
                int r = lr + it * 32;                                             \
                uint32_t off = SW128((uint32_t)(r * 128 + lj * 16));              \
                cp_async16(stb + boffB[t] + off,                                  \
                           opsB[t] + (size_t)(col0 + r) * F + (cc) * 64 + lj * 8, \
                           true);                                                 \
            }                                                                     \
        }                                                                         \
        CP_COMMIT();                                                              \
    } while (0)

    uint32_t ah[2][2][4], al[2][2][4];
    uint32_t bh[2][2][4], bl[2][2][4];

    #define LDFRAGS(stb, ks, q) do {                                              \
        _Pragma("unroll")                                                         \
        for (int mt = 0; mt < 2; mt++) {                                          \
            uint32_t off = SW128((uint32_t)((a_row + mt * 16) * 128 + (ks) * 32 + a_kb)); \
            ldsm_x4(ah[q][mt], (stb) + SA_H + off);                               \
            ldsm_x4(al[q][mt], (stb) + SA_L + off);                               \
        }                                                                         \
        _Pragma("unroll")                                                         \
        for (int ntp = 0; ntp < 2; ntp++) {                                       \
            uint32_t off = SW128((uint32_t)((b_row + ntp * 16) * 128 + (ks) * 32 + b_kb)); \
            ldsm_x4(bh[q][ntp], (stb) + SB_H + off);                              \
            ldsm_x4(bl[q][ntp], (stb) + SB_L + off);                              \
        }                                                                         \
    } while (0)

    LOAD_STAGE(0, 0);

    #pragma unroll
    for (int c = 0; c < 4; c++) {
        CP_WAIT(0);
        __syncthreads();
        if (c + 1 < 4) LOAD_STAGE(c + 1, (c + 1) & 1);
        uint32_t stb = sb + (c & 1) * STAGE_BYTES;
        LDFRAGS(stb, 0, 0);
        #pragma unroll
        for (int ks = 0; ks < 4; ks++) {
            if (ks + 1 < 4) LDFRAGS(stb, ks + 1, (ks + 1) & 1);
            const int q = ks & 1;
            #pragma unroll
            for (int mt = 0; mt < 2; mt++)
                #pragma unroll
                for (int n8 = 0; n8 < 4; n8++) {
                    const uint32_t* bhf = &bh[q][n8 >> 1][(n8 & 1) * 2];
                    const uint32_t* blf = &bl[q][n8 >> 1][(n8 & 1) * 2];
                    mma16816(acc[mt][n8], ah[q][mt], bhf);
                    mma16816(acc[mt][n8], ah[q][mt], blf);
                    mma16816(acc[mt][n8], al[q][mt], bhf);
                }
        }
    }
    #undef LOAD_STAGE
    #undef LDFRAGS

    // ---- epilogue ----
    #pragma unroll
    for (int mt = 0; mt < 2; mt++) {
        #pragma unroll
        for (int half = 0; half < 2; half++) {
            int gr = row0 + wm * 32 + mt * 16 + (lane >> 2) + half * 8;
            bool rowok = gr < M;
            float ps = 0.f, pd = 0.f;
            #pragma unroll
            for (int n8 = 0; n8 < 4; n8++) {
                int gc = col0 + wn * 32 + n8 * 8 + (lane & 3) * 2;
                float v0 = acc[mt][n8][half * 2 + 0];
                float v1 = acc[mt][n8][half * 2 + 1];
                if (bias) { v0 += __ldg(bias + gc); v1 += __ldg(bias + gc + 1); }
                if (rowok) {
                    size_t base = (size_t)gr * F + gc;
                    if (out)
                        *reinterpret_cast<float2*>(out + base) = make_float2(v0, v1);
                    if (write_split) {
                        __nv_bfloat16 h0 = __float2bfloat16(v0);
                        __nv_bfloat16 h1 = __float2bfloat16(v1);
                        __nv_bfloat16 l0 = __float2bfloat16(v0 - __bfloat162float(h0));
                        __nv_bfloat16 l1 = __float2bfloat16(v1 - __bfloat162float(h1));
                        *reinterpret_cast<__nv_bfloat162*>(g_Ah + base) = __nv_bfloat162(h0, h1);
                        *reinterpret_cast<__nv_bfloat162*>(g_Al + base) = __nv_bfloat162(l0, l1);
                    }
                    if (write_splitT) {   // transposed store into Wc slot [n][k]
                        __nv_bfloat16 h0 = __float2bfloat16(v0);
                        __nv_bfloat16 h1 = __float2bfloat16(v1);
                        g_Wh[0][(size_t)gc * F + gr] = h0;
                        g_Wl[0][(size_t)gc * F + gr] =
                            __float2bfloat16(v0 - __bfloat162float(h0));
                        g_Wh[0][(size_t)(gc + 1) * F + gr] = h1;
                        g_Wl[0][(size_t)(gc + 1) * F + gr] =
                            __float2bfloat16(v1 - __bfloat162float(h1));
                    }
                    if (a_src) {
                        ps += v0 * __ldg(a_src + gc) + v1 * __ldg(a_src + gc + 1);
                        pd += v0 * __ldg(a_dst + gc) + v1 * __ldg(a_dst + gc + 1);
                    }
                }
            }
            if (a_src) {
                ps += __shfl_xor_sync(0xffffffffu, ps, 1);
                ps += __shfl_xor_sync(0xffffffffu, ps, 2);
                pd += __shfl_xor_sync(0xffffffffu, pd, 1);
                pd += __shfl_xor_sync(0xffffffffu, pd, 2);
                if (rowok && (lane & 3) == 0) {
                    atomicAdd(&als[gr], ps);
                    atomicAdd(&ald[gr], pd);
                }
            }
        }
    }
}

// ---------------- GAT aggregation: warp per destination node ----------------
// smem-cached edge weights + 2-way unrolled feature gather
__global__ void aggregate_kernel(const float* __restrict__ hW,
                                 const float* __restrict__ bias,
                                 const float* __restrict__ als,
                                 const float* __restrict__ ald_arr,
                                 float* __restrict__ out, int write_split) {
    __shared__ float sw[8][SLOT_CAP];
    int wwarp = threadIdx.x >> 5;
    int node = (blockIdx.x * blockDim.x + threadIdx.x) >> 5;
    int lane = threadIdx.x & 31;
    if (node >= N_NODES) return;
    int beg = node * SLOT_CAP;
    int deg = g_deg[node];
    int end = beg + deg;
    float ald = ald_arr[node];

    // pass 1: compute e_j -> smem, track max (guarded combine)
    float m = -INFINITY;
    for (int j = beg + lane; j < end; j += 32) {
        float e = als[g_srcs[j]] + ald;
        e = (e > 0.f) ? e : NEG_SLOPE * e;
        sw[wwarp][j - beg] = e;
        m = fmaxf(m, e);
    }
    #pragma unroll
    for (int o = 16; o > 0; o >>= 1) m = fmaxf(m, __shfl_xor_sync(0xffffffffu, m, o));
    __syncwarp();
    // pass 2 (smem only): e -> w = exp(e - m), accumulate s
    float s = 0.f;
    for (int j = lane; j < deg; j += 32) {
        float w = __expf(sw[wwarp][j] - m);
        sw[wwarp][j] = w;
        s += w;
    }
    #pragma unroll
    for (int o = 16; o > 0; o >>= 1) s += __shfl_xor_sync(0xffffffffu, s, o);
    float inv = 1.f / (s + EPS_F);
    __syncwarp();

    // feature pass: 2-way unrolled, weights broadcast from smem
    float4 acc0 = make_float4(0.f, 0.f, 0.f, 0.f);
    float4 acc1 = make_float4(0.f, 0.f, 0.f, 0.f);
    float4 acc2 = make_float4(0.f, 0.f, 0.f, 0.f);
    float4 acc3 = make_float4(0.f, 0.f, 0.f, 0.f);
    int j = 0;
    for (; j + 2 <= deg; j += 2) {
        int s0 = g_srcs[beg + j];
        int s1 = g_srcs[beg + j + 1];
        float w0 = sw[wwarp][j];
        float w1 = sw[wwarp][j + 1];
        const float4* h0 = reinterpret_cast<const float4*>(hW + (size_t)s0 * F);
        const float4* h1 = reinterpret_cast<const float4*>(hW + (size_t)s1 * F);
        float4 a0 = __ldg(h0 + lane);
        float4 a1 = __ldg(h0 + lane + 32);
        float4 b0 = __ldg(h1 + lane);
        float4 b1 = __ldg(h1 + lane + 32);
        acc0.x = fmaf(w0, a0.x, acc0.x); acc0.y = fmaf(w0, a0.y, acc0.y);
        acc0.z = fmaf(w0, a0.z, acc0.z); acc0.w = fmaf(w0, a0.w, acc0.w);
        acc1.x = fmaf(w0, a1.x, acc1.x); acc1.y = fmaf(w0, a1.y, acc1.y);
        acc1.z = fmaf(w0, a1.z, acc1.z); acc1.w = fmaf(w0, a1.w, acc1.w);
        acc2.x = fmaf(w1, b0.x, acc2.x); acc2.y = fmaf(w1, b0.y, acc2.y);
        acc2.z = fmaf(w1, b0.z, acc2.z); acc2.w = fmaf(w1, b0.w, acc2.w);
        acc3.x = fmaf(w1, b1.x, acc3.x); acc3.y = fmaf(w1, b1.y, acc3.y);
        acc3.z = fmaf(w1, b1.z, acc3.z); acc3.w = fmaf(w1, b1.w, acc3.w);
    }
    if (j < deg) {
        int s0 = g_srcs[beg + j];
        float w0 = sw[wwarp][j];
        const float4* h0 = reinterpret_cast<const float4*>(hW + (size_t)s0 * F);
        float4 a0 = __ldg(h0 + lane);
        float4 a1 = __ldg(h0 + lane + 32);
        acc0.x = fmaf(w0, a0.x, acc0.x); acc0.y = fmaf(w0, a0.y, acc0.y);
        acc0.z = fmaf(w0, a0.z, acc0.z); acc0.w = fmaf(w0, a0.w, acc0.w);
        acc1.x = fmaf(w0, a1.x, acc1.x); acc1.y = fmaf(w0, a1.y, acc1.y);
        acc1.z = fmaf(w0, a1.z, acc1.z); acc1.w = fmaf(w0, a1.w, acc1.w);
    }
    acc0.x += acc2.x; acc0.y += acc2.y; acc0.z += acc2.z; acc0.w += acc2.w;
    acc1.x += acc3.x; acc1.y += acc3.y; acc1.z += acc3.z; acc1.w += acc3.w;

    const float4* brow = reinterpret_cast<const float4*>(bias);
    float4 b0 = __ldg(brow + lane);
    float4 b1 = __ldg(brow + lane + 32);
    float4 r0 = make_float4(acc0.x * inv + b0.x, acc0.y * inv + b0.y,
                            acc0.z * inv + b0.z, acc0.w * inv + b0.w);
    float4 r1 = make_float4(acc1.x * inv + b1.x, acc1.y * inv + b1.y,
                            acc1.z * inv + b1.z, acc1.w * inv + b1.w);
    if (out) {
        float4* orow = reinterpret_cast<float4*>(out + (size_t)node * F);
        orow[lane] = r0;
        orow[lane + 32] = r1;
    }
    if (write_split) {
        #pragma unroll
        for (int g = 0; g < 2; g++) {
            float4 r = g ? r1 : r0;
            size_t base = (size_t)node * F + (size_t)(lane + g * 32) * 4;
            __nv_bfloat16 h0 = __float2bfloat16(r.x), h1 = __float2bfloat16(r.y);
            __nv_bfloat16 h2 = __float2bfloat16(r.z), h3 = __float2bfloat16(r.w);
            __nv_bfloat16 l0 = __float2bfloat16(r.x - __bfloat162float(h0));
            __nv_bfloat16 l1 = __float2bfloat16(r.y - __bfloat162float(h1));
            __nv_bfloat16 l2 = __float2bfloat16(r.z - __bfloat162float(h2));
            __nv_bfloat16 l3 = __float2bfloat16(r.w - __bfloat162float(h3));
            *reinterpret_cast<__nv_bfloat162*>(g_Ah + base)     = __nv_bfloat162(h0, h1);
            *reinterpret_cast<__nv_bfloat162*>(g_Ah + base + 2) = __nv_bfloat162(h2, h3);
            *reinterpret_cast<__nv_bfloat162*>(g_Al + base)     = __nv_bfloat162(l0, l1);
            *reinterpret_cast<__nv_bfloat162*>(g_Al + base + 2) = __nv_bfloat162(l2, l3);
        }
    }
}

// ---------------- eval-edge dot products + state restore ----------------
#define DOT_B ((E_EVAL * 32 + 255) / 256)     // 12500
#define CLEAN_ELEMS (5 * N_NODES + F)         // deg + 4 al arrays + bc
#define CLEAN_B ((CLEAN_ELEMS + 2047) / 2048) // 25
__global__ void dot_kernel(const float* __restrict__ h,
                           const int* __restrict__ ei,
                           float* __restrict__ out) {
    int b = blockIdx.x;
    if (b >= DOT_B) {
        // restore accumulator state to zero for the next call (graph replay)
        int base = (b - DOT_B) * 2048 + threadIdx.x;
        #pragma unroll
        for (int q = 0; q < 8; q++) {
            int i = base + q * 256;
            if (i < N_NODES) g_deg[i] = 0;
            else if (i < 2 * N_NODES) g_als1[i - N_NODES] = 0.f;
            else if (i < 3 * N_NODES) g_ald1[i - 2 * N_NODES] = 0.f;
            else if (i < 4 * N_NODES) g_als2[i - 3 * N_NODES] = 0.f;
            else if (i < 5 * N_NODES) g_ald2[i - 4 * N_NODES] = 0.f;
            else if (i < 5 * N_NODES + F) g_bc[i - 5 * N_NODES] = 0.f;
        }
        return;
    }
    int eid = (b * blockDim.x + threadIdx.x) >> 5;
    int lane = threadIdx.x & 31;
    if (eid >= E_EVAL) return;
    int a = ei[eid];
    int bb = ei[E_EVAL + eid];
    const float4* ha = reinterpret_cast<const float4*>(h + (size_t)a * F);
    const float4* hb = reinterpret_cast<const float4*>(h + (size_t)bb * F);
    float s = 0.f;
    #pragma unroll
    for (int k = 0; k < 2; k++) {
        float4 va = __ldg(ha + lane + k * 32);
        float4 vb = __ldg(hb + lane + k * 32);
        s = fmaf(va.x, vb.x, s);
        s = fmaf(va.y, vb.y, s);
        s = fmaf(va.z, vb.z, s);
        s = fmaf(va.w, vb.w, s);
    }
    #pragma unroll
    for (int o = 16; o > 0; o >>= 1) s += __shfl_xor_sync(0xffffffffu, s, o);
    if (lane == 0) out[eid] = s;
}

// ---------------- launch ----------------
extern "C" void kernel_launch(void* const* d_in, const int* in_sizes, int n_in,
                              void* d_out, int out_size) {
    const float* x       = (const float*)d_in[0];
    const int*   pos_ei  = (const int*)  d_in[1];
    const int*   ev_ei   = (const int*)  d_in[2];
    const float* Win_W   = (const float*)d_in[3];
    const float* Win_b   = (const float*)d_in[4];
    const float* W1      = (const float*)d_in[5];
    const float* a1_src  = (const float*)d_in[6];
    const float* a1_dst  = (const float*)d_in[7];
    const float* b1      = (const float*)d_in[8];
    const float* W2      = (const float*)d_in[9];
    const float* a2_src  = (const float*)d_in[10];
    const float* a2_dst  = (const float*)d_in[11];
    const float* b2      = (const float*)d_in[12];
    float* out = (float*)d_out;

    float *pA, *pB, *pAls1, *pAld1, *pAls2, *pAld2, *pBc;
    __nv_bfloat16 *pAh, *pAl, *pXh, *pXl, *pW1h, *pW1l, *pWh, *pWl;
    cudaGetSymbolAddress((void**)&pA, g_bufA);
    cudaGetSymbolAddress((void**)&pB, g_bufB);
    cudaGetSymbolAddress((void**)&pAls1, g_als1);
    cudaGetSymbolAddress((void**)&pAld1, g_ald1);
    cudaGetSymbolAddress((void**)&pAls2, g_als2);
    cudaGetSymbolAddress((void**)&pAld2, g_ald2);
    cudaGetSymbolAddress((void**)&pBc, g_bc);
    cudaGetSymbolAddress((void**)&pAh, g_Ah);
    cudaGetSymbolAddress((void**)&pAl, g_Al);
    cudaGetSymbolAddress((void**)&pXh, g_Xh);
    cudaGetSymbolAddress((void**)&pXl, g_Xl);
    cudaGetSymbolAddress((void**)&pW1h, g_W1h);
    cudaGetSymbolAddress((void**)&pW1l, g_W1l);
    cudaGetSymbolAddress((void**)&pWh, g_Wh);
    cudaGetSymbolAddress((void**)&pWl, g_Wl);

    cudaFuncSetAttribute(gemm_mma_kernel,
                         cudaFuncAttributeMaxDynamicSharedMemorySize, SMEM_MMA);

    const dim3 ggrid(2, (N_NODES + 63) / 64);
    const dim3 fgrid(2, F / 64);     // fold gemm: M=256 -> 8 CTAs
    const int warps_blocks_n = (N_NODES * 32 + 255) / 256;

    // fused: scatter + split(x, WinW, W1, W2) + fold_bias (state pre-zeroed)
    work_kernel<<<WORK_B, 256>>>(pos_ei, x, Win_W, W1, W2, Win_b);

    // fold gemm: Wc = Win_W @ W1 -> transposed split into g_Wh[0]/g_Wl[0]
    gemm_mma_kernel<<<fgrid, 256, SMEM_MMA>>>(
        pXh, pXl, pW1h, pW1l, nullptr,
        nullptr, nullptr, nullptr, nullptr,
        nullptr, 0, 1, F);

    // gemm1: hW1 = x @ Wc + bc -> fp32 pA + fused al1
    gemm_mma_kernel<<<ggrid, 256, SMEM_MMA>>>(
        pAh, pAl, pWh + 0 * F * F, pWl + 0 * F * F, pBc,
        a1_src, a1_dst, pAls1, pAld1, pA, 0, 0, N_NODES);
    aggregate_kernel<<<warps_blocks_n, 256>>>(pA, b1, pAls1, pAld1, nullptr, 1);

    // gemm2: hW2 = h1 @ W2 -> fp32 pA + fused al2
    gemm_mma_kernel<<<ggrid, 256, SMEM_MMA>>>(
        pAh, pAl, pWh + 1 * F * F, pWl + 1 * F * F, nullptr,
        a2_src, a2_dst, pAls2, pAld2, pA, 0, 0, N_NODES);
    aggregate_kernel<<<warps_blocks_n, 256>>>(pA, b2, pAls2, pAld2, pB, 0);

    // eval logits + state restore (extra cleanup blocks run concurrently)
    dot_kernel<<<DOT_B + CLEAN_B, 256>>>(pB, ev_ei, out);
}

// round 13
// speedup vs baseline: 1.0153x; 1.0153x over previous
#include <cuda_runtime.h>
#include <cuda_bf16.h>
#include <cuda_fp16.h>
#include <cstdint>
#include <math.h>

#define N_NODES 10000
#define F 256
#define E_POS 320000
#define E_TOT 330000
#define E_EVAL 100000
#define NEG_SLOPE 0.2f
#define EPS_F 1e-16f
#define SLOT_CAP 128

// ---------------- scratch (device globals; zero-initialized at load) ----------------
// g_deg / g_als* / g_ald* / g_bc rely on zero-init for the FIRST call and are
// re-zeroed at the tail of dot_kernel so every call sees identical state.
__device__ float g_bufA[N_NODES * F];     // gemm1 fp32 out
__device__ float g_bufB[N_NODES * F];     // aggregate2 out (final h)
__device__ __half g_bufH[N_NODES * F];    // gemm2 fp16 out (agg2 gather source)
__device__ float g_als1[N_NODES];
__device__ float g_ald1[N_NODES];
__device__ float g_als2[N_NODES];
__device__ float g_ald2[N_NODES];
__device__ float g_bc[F];                 // folded bias Win_b @ W1
__device__ int   g_deg[N_NODES];
__device__ int   g_srcs[N_NODES * SLOT_CAP];
__device__ __nv_bfloat16 g_Ah[N_NODES * F];      // node features split (A operand)
__device__ __nv_bfloat16 g_Al[N_NODES * F];
__device__ __nv_bfloat16 g_Xh[F * F];            // Win_W split, row-major [m][k]
__device__ __nv_bfloat16 g_Xl[F * F];
__device__ __nv_bfloat16 g_W1h[F * F];           // W1 split, transposed [n][k]
__device__ __nv_bfloat16 g_W1l[F * F];
__device__ __nv_bfloat16 g_Wh[2][F * F];         // 0: Wc (fold result), 1: W2 — [n][k]
__device__ __nv_bfloat16 g_Wl[2][F * F];

#define SW128(o) ((o) ^ (((o) >> 3) & 0x70))

__device__ __forceinline__ uint32_t smem_to_u32(const void* p) {
    uint32_t a;
    asm("{ .reg .u64 t; cvta.to.shared.u64 t, %1; cvt.u32.u64 %0, t; }"
        : "=r"(a) : "l"(p));
    return a;
}
__device__ __forceinline__ void ldsm_x4(uint32_t* r, uint32_t addr) {
    asm volatile("ldmatrix.sync.aligned.m8n8.x4.shared.b16 {%0,%1,%2,%3}, [%4];"
        : "=r"(r[0]), "=r"(r[1]), "=r"(r[2]), "=r"(r[3]) : "r"(addr));
}
__device__ __forceinline__ void mma16816(float* c, const uint32_t* a, const uint32_t* b) {
    asm volatile(
        "mma.sync.aligned.m16n8k16.row.col.f32.bf16.bf16.f32 "
        "{%0,%1,%2,%3}, {%4,%5,%6,%7}, {%8,%9}, {%0,%1,%2,%3};"
        : "+f"(c[0]), "+f"(c[1]), "+f"(c[2]), "+f"(c[3])
        : "r"(a[0]), "r"(a[1]), "r"(a[2]), "r"(a[3]), "r"(b[0]), "r"(b[1]));
}
__device__ __forceinline__ void cp_async16(uint32_t saddr, const void* g, bool valid) {
    int sz = valid ? 16 : 0;
    asm volatile("cp.async.cg.shared.global [%0], [%1], 16, %2;"
        :: "r"(saddr), "l"(g), "r"(sz) : "memory");
}
#define CP_COMMIT() asm volatile("cp.async.commit_group;" ::: "memory")
#define CP_WAIT(n)  asm volatile("cp.async.wait_group %0;" :: "n"(n) : "memory")

// ---------------- fused independent work: scatter + split + fold_bias ----------------
#define E_Q (E_TOT / 4)                          // 82500
#define SC_B ((E_Q + 255) / 256)                 // 323
#define M4_A (N_NODES * F / 4)                   // 640000
#define SP_B ((M4_A + 3 * F * F + 255) / 256)
#define FB_B (F / 32)                            // 8
#define WORK_B (SC_B + SP_B + FB_B)

__global__ void work_kernel(const int* __restrict__ pos_ei,
                            const float* __restrict__ x,
                            const float* __restrict__ WinW,
                            const float* __restrict__ W1,
                            const float* __restrict__ W2,
                            const float* __restrict__ Win_b) {
    int b = blockIdx.x;
    if (b < SC_B) {
        int gid = b * blockDim.x + threadIdx.x;
        if (gid >= E_Q) return;
        #pragma unroll
        for (int q = 0; q < 4; q++) {
            int e = gid + q * E_Q;
            int src, dst;
            if (e < E_POS) { src = __ldg(pos_ei + e); dst = __ldg(pos_ei + E_POS + e); }
            else           { src = e - E_POS; dst = src; }
            int pos = atomicAdd(&g_deg[dst], 1);
            if (pos < SLOT_CAP) g_srcs[dst * SLOT_CAP + pos] = src;
        }
    } else if (b < SC_B + SP_B) {
        int idx = (b - SC_B) * blockDim.x + threadIdx.x;
        if (idx < M4_A) {
            float4 v = reinterpret_cast<const float4*>(x)[idx];
            __nv_bfloat16 h0 = __float2bfloat16(v.x), h1 = __float2bfloat16(v.y);
            __nv_bfloat16 h2 = __float2bfloat16(v.z), h3 = __float2bfloat16(v.w);
            __nv_bfloat16 l0 = __float2bfloat16(v.x - __bfloat162float(h0));
            __nv_bfloat16 l1 = __float2bfloat16(v.y - __bfloat162float(h1));
            __nv_bfloat16 l2 = __float2bfloat16(v.z - __bfloat162float(h2));
            __nv_bfloat16 l3 = __float2bfloat16(v.w - __bfloat162float(h3));
            __nv_bfloat162* ph = reinterpret_cast<__nv_bfloat162*>(g_Ah);
            __nv_bfloat162* pl = reinterpret_cast<__nv_bfloat162*>(g_Al);
            ph[idx * 2]     = __nv_bfloat162(h0, h1);
            ph[idx * 2 + 1] = __nv_bfloat162(h2, h3);
            pl[idx * 2]     = __nv_bfloat162(l0, l1);
            pl[idx * 2 + 1] = __nv_bfloat162(l2, l3);
        } else {
            int i2 = idx - M4_A;
            if (i2 < 3 * F * F) {
                int w = i2 >> 16;
                int j = i2 & 65535;
                int k = j >> 8, n = j & 255;
                if (w == 0) {
                    float v = __ldg(WinW + j);
                    __nv_bfloat16 h = __float2bfloat16(v);
                    g_Xh[j] = h;
                    g_Xl[j] = __float2bfloat16(v - __bfloat162float(h));
                } else if (w == 1) {
                    float v = __ldg(W1 + j);
                    __nv_bfloat16 h = __float2bfloat16(v);
                    g_W1h[n * F + k] = h;
                    g_W1l[n * F + k] = __float2bfloat16(v - __bfloat162float(h));
                } else {
                    float v = __ldg(W2 + j);
                    __nv_bfloat16 h = __float2bfloat16(v);
                    g_Wh[1][n * F + k] = h;
                    g_Wl[1][n * F + k] = __float2bfloat16(v - __bfloat162float(h));
                }
            }
        }
    } else {
        int n = threadIdx.x;
        int k0 = (b - SC_B - SP_B) * 32;
        float s = 0.f;
        #pragma unroll
        for (int kk = 0; kk < 32; kk++) {
            int k = k0 + kk;
            s = fmaf(__ldg(Win_b + k), __ldg(W1 + (size_t)k * F + n), s);
        }
        atomicAdd(&g_bc[n], s);
    }
}

// ---------------- pipelined HMMA GEMM ----------------
#define SA_H 0
#define SA_L 8192
#define SB_H 16384
#define SB_L 32768
#define STAGE_BYTES 49152
#define SMEM_MMA (2 * STAGE_BYTES + 1024)

__global__ __launch_bounds__(256, 2) void gemm_mma_kernel(
    const __nv_bfloat16* __restrict__ Ah, const __nv_bfloat16* __restrict__ Al,
    const __nv_bfloat16* __restrict__ Bh, const __nv_bfloat16* __restrict__ Bl,
    const float* __restrict__ bias,
    const float* __restrict__ a_src, const float* __restrict__ a_dst,
    float* __restrict__ als, float* __restrict__ ald,
    float* __restrict__ out, __half* __restrict__ out_h,
    int write_split, int write_splitT, int M) {
    extern __shared__ char dsmem[];
    const int tid = threadIdx.x;
    const int wid = tid >> 5;
    const int lane = tid & 31;
    const int wm = wid >> 2;
    const int wn = wid & 3;
    const int row0 = blockIdx.y * 64;
    const int col0 = blockIdx.x * 128;

    uint32_t dsb = smem_to_u32(dsmem);
    uint32_t sb = (dsb + 1023) & ~1023u;

    float acc[2][4][4] = {};

    const int a_row = wm * 32 + (lane & 15);
    const int a_kb  = (lane >> 4) * 16;
    const int b_row = wn * 32 + (lane & 7) + ((lane >> 4) & 1) * 8;
    const int b_kb  = ((lane >> 3) & 1) * 16;

    const __nv_bfloat16* opsA[2] = { Ah, Al };
    const __nv_bfloat16* opsB[2] = { Bh, Bl };
    const int boffA[2] = { SA_H, SA_L };
    const int boffB[2] = { SB_H, SB_L };

    const int lr = tid >> 3;
    const int lj = tid & 7;

    #define LOAD_STAGE(cc, ss) do {                                              \
        uint32_t stb = sb + (ss) * STAGE_BYTES;                                   \
        _Pragma("unroll")                                                         \
        for (int t = 0; t < 2; t++) {                                             \
            _Pragma("unroll")                                                     \
            for (int it = 0; it < 2; it++) {                                      \
                int r = lr + it * 32;                                             \
                int grow = row0 + r;                                              \
                uint32_t off = SW128((uint32_t)(r * 128 + lj * 16));              \
                cp_async16(stb + boffA[t] + off,                                  \
                           opsA[t] + (size_t)grow * F + (cc) * 64 + lj * 8,       \
                           grow < M);                                             \
            }                                                                     \
        }                                                                         \
        _Pragma("unroll")                                                         \
        for (int t = 0; t < 2; t++) {                                             \
            _Pragma("unroll")                                                     \
            for (int it = 0; it < 4; it++) {                                      \
                int r = lr + it * 32;                                             \
                uint32_t off = SW128((uint32_t)(r * 128 + lj * 16));              \
                cp_async16(stb + boffB[t] + off,                                  \
                           opsB[t] + (size_t)(col0 + r) * F + (cc) * 64 + lj * 8, \
                           true);                                                 \
            }                                                                     \
        }                                                                         \
        CP_COMMIT();                                                              \
    } while (0)

    uint32_t ah[2][2][4], al[2][2][4];
    uint32_t bh[2][2][4], bl[2][2][4];

    #define LDFRAGS(stb, ks, q) do {                                              \
        _Pragma("unroll")                                                         \
        for (int mt = 0; mt < 2; mt++) {                                          \
            uint32_t off = SW128((uint32_t)((a_row + mt * 16) * 128 + (ks) * 32 + a_kb)); \
            ldsm_x4(ah[q][mt], (stb) + SA_H + off);                               \
            ldsm_x4(al[q][mt], (stb) + SA_L + off);                               \
        }                                                                         \
        _Pragma("unroll")                                                         \
        for (int ntp = 0; ntp < 2; ntp++) {                                       \
            uint32_t off = SW128((uint32_t)((b_row + ntp * 16) * 128 + (ks) * 32 + b_kb)); \
            ldsm_x4(bh[q][ntp], (stb) + SB_H + off);                              \
            ldsm_x4(bl[q][ntp], (stb) + SB_L + off);                              \
        }                                                                         \
    } while (0)

    LOAD_STAGE(0, 0);

    #pragma unroll
    for (int c = 0; c < 4; c++) {
        CP_WAIT(0);
        __syncthreads();
        if (c + 1 < 4) LOAD_STAGE(c + 1, (c + 1) & 1);
        uint32_t stb = sb + (c & 1) * STAGE_BYTES;
        LDFRAGS(stb, 0, 0);
        #pragma unroll
        for (int ks = 0; ks < 4; ks++) {
            if (ks + 1 < 4) LDFRAGS(stb, ks + 1, (ks + 1) & 1);
            const int q = ks & 1;
            #pragma unroll
            for (int mt = 0; mt < 2; mt++)
                #pragma unroll
                for (int n8 = 0; n8 < 4; n8++) {
                    const uint32_t* bhf = &bh[q][n8 >> 1][(n8 & 1) * 2];
                    const uint32_t* blf = &bl[q][n8 >> 1][(n8 & 1) * 2];
                    mma16816(acc[mt][n8], ah[q][mt], bhf);
                    mma16816(acc[mt][n8], ah[q][mt], blf);
                    mma16816(acc[mt][n8], al[q][mt], bhf);
                }
        }
    }
    #undef LOAD_STAGE
    #undef LDFRAGS

    // ---- epilogue ----
    #pragma unroll
    for (int mt = 0; mt < 2; mt++) {
        #pragma unroll
        for (int half = 0; half < 2; half++) {
            int gr = row0 + wm * 32 + mt * 16 + (lane >> 2) + half * 8;
            bool rowok = gr < M;
            float ps = 0.f, pd = 0.f;
            #pragma unroll
            for (int n8 = 0; n8 < 4; n8++) {
                int gc = col0 + wn * 32 + n8 * 8 + (lane & 3) * 2;
                float v0 = acc[mt][n8][half * 2 + 0];
                float v1 = acc[mt][n8][half * 2 + 1];
                if (bias) { v0 += __ldg(bias + gc); v1 += __ldg(bias + gc + 1); }
                if (rowok) {
                    size_t base = (size_t)gr * F + gc;
                    if (out)
                        *reinterpret_cast<float2*>(out + base) = make_float2(v0, v1);
                    if (out_h)
                        *reinterpret_cast<__half2*>(out_h + base) = __floats2half2_rn(v0, v1);
                    if (write_split) {
                        __nv_bfloat16 h0 = __float2bfloat16(v0);
                        __nv_bfloat16 h1 = __float2bfloat16(v1);
                        __nv_bfloat16 l0 = __float2bfloat16(v0 - __bfloat162float(h0));
                        __nv_bfloat16 l1 = __float2bfloat16(v1 - __bfloat162float(h1));
                        *reinterpret_cast<__nv_bfloat162*>(g_Ah + base) = __nv_bfloat162(h0, h1);
                        *reinterpret_cast<__nv_bfloat162*>(g_Al + base) = __nv_bfloat162(l0, l1);
                    }
                    if (write_splitT) {   // transposed store into Wc slot [n][k]
                        __nv_bfloat16 h0 = __float2bfloat16(v0);
                        __nv_bfloat16 h1 = __float2bfloat16(v1);
                        g_Wh[0][(size_t)gc * F + gr] = h0;
                        g_Wl[0][(size_t)gc * F + gr] =
                            __float2bfloat16(v0 - __bfloat162float(h0));
                        g_Wh[0][(size_t)(gc + 1) * F + gr] = h1;
                        g_Wl[0][(size_t)(gc + 1) * F + gr] =
                            __float2bfloat16(v1 - __bfloat162float(h1));
                    }
                    if (a_src) {
                        ps += v0 * __ldg(a_src + gc) + v1 * __ldg(a_src + gc + 1);
                        pd += v0 * __ldg(a_dst + gc) + v1 * __ldg(a_dst + gc + 1);
                    }
                }
            }
            if (a_src) {
                ps += __shfl_xor_sync(0xffffffffu, ps, 1);
                ps += __shfl_xor_sync(0xffffffffu, ps, 2);
                pd += __shfl_xor_sync(0xffffffffu, pd, 1);
                pd += __shfl_xor_sync(0xffffffffu, pd, 2);
                if (rowok && (lane & 3) == 0) {
                    atomicAdd(&als[gr], ps);
                    atomicAdd(&ald[gr], pd);
                }
            }
        }
    }
}

// ---------------- GAT aggregation: warp per destination node (R11 structure) ----------------
// hW: fp32 features (layer 1) OR hH: fp16 features (layer 2) — exactly one non-null.
__global__ void aggregate_kernel(const float* __restrict__ hW,
                                 const __half* __restrict__ hH,
                                 const float* __restrict__ bias,
                                 const float* __restrict__ als,
                                 const float* __restrict__ ald_arr,
                                 float* __restrict__ out, int write_split) {
    int node = (blockIdx.x * blockDim.x + threadIdx.x) >> 5;
    int lane = threadIdx.x & 31;
    if (node >= N_NODES) return;
    int beg = node * SLOT_CAP;
    int end = beg + g_deg[node];
    float ald = ald_arr[node];
    // online softmax over this lane's strided subset
    float m = -INFINITY, s = 0.f;
    for (int j = beg + lane; j < end; j += 32) {
        float e = als[g_srcs[j]] + ald;
        e = (e > 0.f) ? e : NEG_SLOPE * e;
        if (e > m) { s = s * __expf(m - e) + 1.f; m = e; }
        else       { s += __expf(e - m); }
    }
    // warp-combine (m, s) — guard -INF lanes
    #pragma unroll
    for (int o = 16; o > 0; o >>= 1) {
        float mo = __shfl_xor_sync(0xffffffffu, m, o);
        float so = __shfl_xor_sync(0xffffffffu, s, o);
        float mn = fmaxf(m, mo);
        float sc  = (m  == -INFINITY) ? 0.f : __expf(m  - mn);
        float sco = (mo == -INFINITY) ? 0.f : __expf(mo - mn);
        s = s * sc + so * sco;
        m = mn;
    }
    float inv = 1.f / (s + EPS_F);
    float4 acc0 = make_float4(0.f, 0.f, 0.f, 0.f);
    float4 acc1 = make_float4(0.f, 0.f, 0.f, 0.f);
    if (hW) {
        for (int j = beg; j < end; j++) {
            int src = g_srcs[j];
            float e = als[src] + ald;
            e = (e > 0.f) ? e : NEG_SLOPE * e;
            float w = __expf(e - m);
            const float4* hr = reinterpret_cast<const float4*>(hW + (size_t)src * F);
            float4 v0 = __ldg(hr + lane);
            float4 v1 = __ldg(hr + lane + 32);
            acc0.x = fmaf(w, v0.x, acc0.x); acc0.y = fmaf(w, v0.y, acc0.y);
            acc0.z = fmaf(w, v0.z, acc0.z); acc0.w = fmaf(w, v0.w, acc0.w);
            acc1.x = fmaf(w, v1.x, acc1.x); acc1.y = fmaf(w, v1.y, acc1.y);
            acc1.z = fmaf(w, v1.z, acc1.z); acc1.w = fmaf(w, v1.w, acc1.w);
        }
    } else {
        // fp16 gather: one LDG.128 per neighbor (8 halves = this lane's 8 features)
        for (int j = beg; j < end; j++) {
            int src = g_srcs[j];
            float e = als[src] + ald;
            e = (e > 0.f) ? e : NEG_SLOPE * e;
            float w = __expf(e - m);
            const uint4* hr = reinterpret_cast<const uint4*>(hH + (size_t)src * F);
            uint4 v = __ldg(hr + lane);
            const __half2* hp = reinterpret_cast<const __half2*>(&v);
            float2 f0 = __half22float2(hp[0]);
            float2 f1 = __half22float2(hp[1]);
            float2 f2 = __half22float2(hp[2]);
            float2 f3 = __half22float2(hp[3]);
            acc0.x = fmaf(w, f0.x, acc0.x); acc0.y = fmaf(w, f0.y, acc0.y);
            acc0.z = fmaf(w, f1.x, acc0.z); acc0.w = fmaf(w, f1.y, acc0.w);
            acc1.x = fmaf(w, f2.x, acc1.x); acc1.y = fmaf(w, f2.y, acc1.y);
            acc1.z = fmaf(w, f3.x, acc1.z); acc1.w = fmaf(w, f3.y, acc1.w);
        }
    }
    // NOTE: fp16 path accumulates this lane's 8 CONTIGUOUS features (lane*8..lane*8+7)
    // while fp32 path uses strided float4s. Output indexing differs accordingly.
    const float4* brow = reinterpret_cast<const float4*>(bias);
    if (hW) {
        float4 b0 = __ldg(brow + lane);
        float4 b1 = __ldg(brow + lane + 32);
        float4 r0 = make_float4(acc0.x * inv + b0.x, acc0.y * inv + b0.y,
                                acc0.z * inv + b0.z, acc0.w * inv + b0.w);
        float4 r1 = make_float4(acc1.x * inv + b1.x, acc1.y * inv + b1.y,
                                acc1.z * inv + b1.z, acc1.w * inv + b1.w);
        if (out) {
            float4* orow = reinterpret_cast<float4*>(out + (size_t)node * F);
            orow[lane] = r0;
            orow[lane + 32] = r1;
        }
        if (write_split) {
            #pragma unroll
            for (int g = 0; g < 2; g++) {
                float4 r = g ? r1 : r0;
                size_t base = (size_t)node * F + (size_t)(lane + g * 32) * 4;
                __nv_bfloat16 h0 = __float2bfloat16(r.x), h1 = __float2bfloat16(r.y);
                __nv_bfloat16 h2 = __float2bfloat16(r.z), h3 = __float2bfloat16(r.w);
                __nv_bfloat16 l0 = __float2bfloat16(r.x - __bfloat162float(h0));
                __nv_bfloat16 l1 = __float2bfloat16(r.y - __bfloat162float(h1));
                __nv_bfloat16 l2 = __float2bfloat16(r.z - __bfloat162float(h2));
                __nv_bfloat16 l3 = __float2bfloat16(r.w - __bfloat162float(h3));
                *reinterpret_cast<__nv_bfloat162*>(g_Ah + base)     = __nv_bfloat162(h0, h1);
                *reinterpret_cast<__nv_bfloat162*>(g_Ah + base + 2) = __nv_bfloat162(h2, h3);
                *reinterpret_cast<__nv_bfloat162*>(g_Al + base)     = __nv_bfloat162(l0, l1);
                *reinterpret_cast<__nv_bfloat162*>(g_Al + base + 2) = __nv_bfloat162(l2, l3);
            }
        }
    } else {
        // fp16 path: features lane*8 .. lane*8+7 (two contiguous float4 stores)
        size_t base = (size_t)node * F + (size_t)lane * 8;
        const float* bp = bias + lane * 8;
        float4 r0 = make_float4(acc0.x * inv + __ldg(bp + 0), acc0.y * inv + __ldg(bp + 1),
                                acc0.z * inv + __ldg(bp + 2), acc0.w * inv + __ldg(bp + 3));
        float4 r1 = make_float4(acc1.x * inv + __ldg(bp + 4), acc1.y * inv + __ldg(bp + 5),
                                acc1.z * inv + __ldg(bp + 6), acc1.w * inv + __ldg(bp + 7));
        *reinterpret_cast<float4*>(out + base)     = r0;
        *reinterpret_cast<float4*>(out + base + 4) = r1;
    }
}

// ---------------- eval-edge dot products + state restore ----------------
#define DOT_B ((E_EVAL * 32 + 255) / 256)     // 12500
#define CLEAN_ELEMS (5 * N_NODES + F)         // deg + 4 al arrays + bc
#define CLEAN_B ((CLEAN_ELEMS + 2047) / 2048) // 25
__global__ void dot_kernel(const float* __restrict__ h,
                           const int* __restrict__ ei,
                           float* __restrict__ out) {
    int b = blockIdx.x;
    if (b >= DOT_B) {
        int base = (b - DOT_B) * 2048 + threadIdx.x;
        #pragma unroll
        for (int q = 0; q < 8; q++) {
            int i = base + q * 256;
            if (i < N_NODES) g_deg[i] = 0;
            else if (i < 2 * N_NODES) g_als1[i - N_NODES] = 0.f;
            else if (i < 3 * N_NODES) g_ald1[i - 2 * N_NODES] = 0.f;
            else if (i < 4 * N_NODES) g_als2[i - 3 * N_NODES] = 0.f;
            else if (i < 5 * N_NODES) g_ald2[i - 4 * N_NODES] = 0.f;
            else if (i < 5 * N_NODES + F) g_bc[i - 5 * N_NODES] = 0.f;
        }
        return;
    }
    int eid = (b * blockDim.x + threadIdx.x) >> 5;
    int lane = threadIdx.x & 31;
    if (eid >= E_EVAL) return;
    int a = ei[eid];
    int bb = ei[E_EVAL + eid];
    const float4* ha = reinterpret_cast<const float4*>(h + (size_t)a * F);
    const float4* hb = reinterpret_cast<const float4*>(h + (size_t)bb * F);
    float s = 0.f;
    #pragma unroll
    for (int k = 0; k < 2; k++) {
        float4 va = __ldg(ha + lane + k * 32);
        float4 vb = __ldg(hb + lane + k * 32);
        s = fmaf(va.x, vb.x, s);
        s = fmaf(va.y, vb.y, s);
        s = fmaf(va.z, vb.z, s);
        s = fmaf(va.w, vb.w, s);
    }
    #pragma unroll
    for (int o = 16; o > 0; o >>= 1) s += __shfl_xor_sync(0xffffffffu, s, o);
    if (lane == 0) out[eid] = s;
}

// ---------------- launch ----------------
extern "C" void kernel_launch(void* const* d_in, const int* in_sizes, int n_in,
                              void* d_out, int out_size) {
    const float* x       = (const float*)d_in[0];
    const int*   pos_ei  = (const int*)  d_in[1];
    const int*   ev_ei   = (const int*)  d_in[2];
    const float* Win_W   = (const float*)d_in[3];
    const float* Win_b   = (const float*)d_in[4];
    const float* W1      = (const float*)d_in[5];
    const float* a1_src  = (const float*)d_in[6];
    const float* a1_dst  = (const float*)d_in[7];
    const float* b1      = (const float*)d_in[8];
    const float* W2      = (const float*)d_in[9];
    const float* a2_src  = (const float*)d_in[10];
    const float* a2_dst  = (const float*)d_in[11];
    const float* b2      = (const float*)d_in[12];
    float* out = (float*)d_out;

    float *pA, *pB, *pAls1, *pAld1, *pAls2, *pAld2, *pBc;
    __half *pH;
    __nv_bfloat16 *pAh, *pAl, *pXh, *pXl, *pW1h, *pW1l, *pWh, *pWl;
    cudaGetSymbolAddress((void**)&pA, g_bufA);
    cudaGetSymbolAddress((void**)&pB, g_bufB);
    cudaGetSymbolAddress((void**)&pH, g_bufH);
    cudaGetSymbolAddress((void**)&pAls1, g_als1);
    cudaGetSymbolAddress((void**)&pAld1, g_ald1);
    cudaGetSymbolAddress((void**)&pAls2, g_als2);
    cudaGetSymbolAddress((void**)&pAld2, g_ald2);
    cudaGetSymbolAddress((void**)&pBc, g_bc);
    cudaGetSymbolAddress((void**)&pAh, g_Ah);
    cudaGetSymbolAddress((void**)&pAl, g_Al);
    cudaGetSymbolAddress((void**)&pXh, g_Xh);
    cudaGetSymbolAddress((void**)&pXl, g_Xl);
    cudaGetSymbolAddress((void**)&pW1h, g_W1h);
    cudaGetSymbolAddress((void**)&pW1l, g_W1l);
    cudaGetSymbolAddress((void**)&pWh, g_Wh);
    cudaGetSymbolAddress((void**)&pWl, g_Wl);

    cudaFuncSetAttribute(gemm_mma_kernel,
                         cudaFuncAttributeMaxDynamicSharedMemorySize, SMEM_MMA);

    const dim3 ggrid(2, (N_NODES + 63) / 64);
    const dim3 fgrid(2, F / 64);     // fold gemm: M=256 -> 8 CTAs
    const int warps_blocks_n = (N_NODES * 32 + 255) / 256;

    // fused: scatter + split(x, WinW, W1, W2) + fold_bias (state pre-zeroed)
    work_kernel<<<WORK_B, 256>>>(pos_ei, x, Win_W, W1, W2, Win_b);

    // fold gemm: Wc = Win_W @ W1 -> transposed split into g_Wh[0]/g_Wl[0]
    gemm_mma_kernel<<<fgrid, 256, SMEM_MMA>>>(
        pXh, pXl, pW1h, pW1l, nullptr,
        nullptr, nullptr, nullptr, nullptr,
        nullptr, nullptr, 0, 1, F);

    // gemm1: hW1 = x @ Wc + bc -> fp32 pA + fused al1
    gemm_mma_kernel<<<ggrid, 256, SMEM_MMA>>>(
        pAh, pAl, pWh + 0 * F * F, pWl + 0 * F * F, pBc,
        a1_src, a1_dst, pAls1, pAld1, pA, nullptr, 0, 0, N_NODES);
    // aggregate layer1 (fp32 gather) -> bf16 split for gemm2
    aggregate_kernel<<<warps_blocks_n, 256>>>(pA, nullptr, b1, pAls1, pAld1, nullptr, 1);

    // gemm2: hW2 = h1 @ W2 -> fp16 pH + fused al2 (fp32 accum)
    gemm_mma_kernel<<<ggrid, 256, SMEM_MMA>>>(
        pAh, pAl, pWh + 1 * F * F, pWl + 1 * F * F, nullptr,
        a2_src, a2_dst, pAls2, pAld2, nullptr, pH, 0, 0, N_NODES);
    // aggregate layer2 (fp16 gather) -> fp32 pB for dot
    aggregate_kernel<<<warps_blocks_n, 256>>>(nullptr, pH, b2, pAls2, pAld2, pB, 0);

    // eval logits + state restore (extra cleanup blocks run concurrently)
    dot_kernel<<<DOT_B + CLEAN_B, 256>>>(pB, ev_ei, out);
}

// round 14
// speedup vs baseline: 1.1874x; 1.1695x over previous
#include <cuda_runtime.h>
#include <cuda_bf16.h>
#include <cuda_fp16.h>
#include <cstdint>
#include <math.h>

#define N_NODES 10000
#define F 256
#define E_POS 320000
#define E_TOT 330000
#define E_EVAL 100000
#define NEG_SLOPE 0.2f
#define EPS_F 1e-16f
#define SLOT_CAP 128

// ---------------- scratch (device globals; zero-initialized at load) ----------------
// g_deg / g_als* / g_ald* / g_bc rely on zero-init for the FIRST call and are
// re-zeroed at the tail of dot_kernel so every call sees identical state.
__device__ float g_bufB[N_NODES * F];     // aggregate2 out (final h, fp32 for dot)
__device__ __half g_bufH[N_NODES * F];    // gemm fp16 out (aggregate gather source)
__device__ float g_als1[N_NODES];
__device__ float g_ald1[N_NODES];
__device__ float g_als2[N_NODES];
__device__ float g_ald2[N_NODES];
__device__ float g_bc[F];                 // folded bias Win_b @ W1
__device__ int   g_deg[N_NODES];
__device__ int   g_srcs[N_NODES * SLOT_CAP];
__device__ __nv_bfloat16 g_Ah[N_NODES * F];      // node features split (A operand)
__device__ __nv_bfloat16 g_Al[N_NODES * F];
__device__ __nv_bfloat16 g_Xh[F * F];            // Win_W split, row-major [m][k]
__device__ __nv_bfloat16 g_Xl[F * F];
__device__ __nv_bfloat16 g_W1h[F * F];           // W1 split, transposed [n][k]
__device__ __nv_bfloat16 g_W1l[F * F];
__device__ __nv_bfloat16 g_Wh[2][F * F];         // 0: Wc (fold result), 1: W2 — [n][k]
__device__ __nv_bfloat16 g_Wl[2][F * F];

#define SW128(o) ((o) ^ (((o) >> 3) & 0x70))

__device__ __forceinline__ uint32_t smem_to_u32(const void* p) {
    uint32_t a;
    asm("{ .reg .u64 t; cvta.to.shared.u64 t, %1; cvt.u32.u64 %0, t; }"
        : "=r"(a) : "l"(p));
    return a;
}
__device__ __forceinline__ void ldsm_x4(uint32_t* r, uint32_t addr) {
    asm volatile("ldmatrix.sync.aligned.m8n8.x4.shared.b16 {%0,%1,%2,%3}, [%4];"
        : "=r"(r[0]), "=r"(r[1]), "=r"(r[2]), "=r"(r[3]) : "r"(addr));
}
__device__ __forceinline__ void mma16816(float* c, const uint32_t* a, const uint32_t* b) {
    asm volatile(
        "mma.sync.aligned.m16n8k16.row.col.f32.bf16.bf16.f32 "
        "{%0,%1,%2,%3}, {%4,%5,%6,%7}, {%8,%9}, {%0,%1,%2,%3};"
        : "+f"(c[0]), "+f"(c[1]), "+f"(c[2]), "+f"(c[3])
        : "r"(a[0]), "r"(a[1]), "r"(a[2]), "r"(a[3]), "r"(b[0]), "r"(b[1]));
}
__device__ __forceinline__ void cp_async16(uint32_t saddr, const void* g, bool valid) {
    int sz = valid ? 16 : 0;
    asm volatile("cp.async.cg.shared.global [%0], [%1], 16, %2;"
        :: "r"(saddr), "l"(g), "r"(sz) : "memory");
}
#define CP_COMMIT() asm volatile("cp.async.commit_group;" ::: "memory")
#define CP_WAIT(n)  asm volatile("cp.async.wait_group %0;" :: "n"(n) : "memory")

// ---------------- fused independent work: scatter + split + fold_bias ----------------
#define E_Q (E_TOT / 4)                          // 82500
#define SC_B ((E_Q + 255) / 256)                 // 323
#define M4_A (N_NODES * F / 4)                   // 640000
#define SP_B ((M4_A + 3 * F * F + 255) / 256)
#define FB_B (F / 32)                            // 8
#define WORK_B (SC_B + SP_B + FB_B)

__global__ void work_kernel(const int* __restrict__ pos_ei,
                            const float* __restrict__ x,
                            const float* __restrict__ WinW,
                            const float* __restrict__ W1,
                            const float* __restrict__ W2,
                            const float* __restrict__ Win_b) {
    int b = blockIdx.x;
    if (b < SC_B) {
        int gid = b * blockDim.x + threadIdx.x;
        if (gid >= E_Q) return;
        #pragma unroll
        for (int q = 0; q < 4; q++) {
            int e = gid + q * E_Q;
            int src, dst;
            if (e < E_POS) { src = __ldg(pos_ei + e); dst = __ldg(pos_ei + E_POS + e); }
            else           { src = e - E_POS; dst = src; }
            int pos = atomicAdd(&g_deg[dst], 1);
            if (pos < SLOT_CAP) g_srcs[dst * SLOT_CAP + pos] = src;
        }
    } else if (b < SC_B + SP_B) {
        int idx = (b - SC_B) * blockDim.x + threadIdx.x;
        if (idx < M4_A) {
            float4 v = reinterpret_cast<const float4*>(x)[idx];
            __nv_bfloat16 h0 = __float2bfloat16(v.x), h1 = __float2bfloat16(v.y);
            __nv_bfloat16 h2 = __float2bfloat16(v.z), h3 = __float2bfloat16(v.w);
            __nv_bfloat16 l0 = __float2bfloat16(v.x - __bfloat162float(h0));
            __nv_bfloat16 l1 = __float2bfloat16(v.y - __bfloat162float(h1));
            __nv_bfloat16 l2 = __float2bfloat16(v.z - __bfloat162float(h2));
            __nv_bfloat16 l3 = __float2bfloat16(v.w - __bfloat162float(h3));
            __nv_bfloat162* ph = reinterpret_cast<__nv_bfloat162*>(g_Ah);
            __nv_bfloat162* pl = reinterpret_cast<__nv_bfloat162*>(g_Al);
            ph[idx * 2]     = __nv_bfloat162(h0, h1);
            ph[idx * 2 + 1] = __nv_bfloat162(h2, h3);
            pl[idx * 2]     = __nv_bfloat162(l0, l1);
            pl[idx * 2 + 1] = __nv_bfloat162(l2, l3);
        } else {
            int i2 = idx - M4_A;
            if (i2 < 3 * F * F) {
                int w = i2 >> 16;
                int j = i2 & 65535;
                int k = j >> 8, n = j & 255;
                if (w == 0) {
                    float v = __ldg(WinW + j);
                    __nv_bfloat16 h = __float2bfloat16(v);
                    g_Xh[j] = h;
                    g_Xl[j] = __float2bfloat16(v - __bfloat162float(h));
                } else if (w == 1) {
                    float v = __ldg(W1 + j);
                    __nv_bfloat16 h = __float2bfloat16(v);
                    g_W1h[n * F + k] = h;
                    g_W1l[n * F + k] = __float2bfloat16(v - __bfloat162float(h));
                } else {
                    float v = __ldg(W2 + j);
                    __nv_bfloat16 h = __float2bfloat16(v);
                    g_Wh[1][n * F + k] = h;
                    g_Wl[1][n * F + k] = __float2bfloat16(v - __bfloat162float(h));
                }
            }
        }
    } else {
        int n = threadIdx.x;
        int k0 = (b - SC_B - SP_B) * 32;
        float s = 0.f;
        #pragma unroll
        for (int kk = 0; kk < 32; kk++) {
            int k = k0 + kk;
            s = fmaf(__ldg(Win_b + k), __ldg(W1 + (size_t)k * F + n), s);
        }
        atomicAdd(&g_bc[n], s);
    }
}

// ---------------- pipelined HMMA GEMM ----------------
#define SA_H 0
#define SA_L 8192
#define SB_H 16384
#define SB_L 32768
#define STAGE_BYTES 49152
#define SMEM_MMA (2 * STAGE_BYTES + 1024)

__global__ __launch_bounds__(256, 2) void gemm_mma_kernel(
    const __nv_bfloat16* __restrict__ Ah, const __nv_bfloat16* __restrict__ Al,
    const __nv_bfloat16* __restrict__ Bh, const __nv_bfloat16* __restrict__ Bl,
    const float* __restrict__ bias,
    const float* __restrict__ a_src, const float* __restrict__ a_dst,
    float* __restrict__ als, float* __restrict__ ald,
    __half* __restrict__ out_h,
    int write_splitT, int M) {
    extern __shared__ char dsmem[];
    const int tid = threadIdx.x;
    const int wid = tid >> 5;
    const int lane = tid & 31;
    const int wm = wid >> 2;
    const int wn = wid & 3;
    const int row0 = blockIdx.y * 64;
    const int col0 = blockIdx.x * 128;

    uint32_t dsb = smem_to_u32(dsmem);
    uint32_t sb = (dsb + 1023) & ~1023u;

    float acc[2][4][4] = {};

    const int a_row = wm * 32 + (lane & 15);
    const int a_kb  = (lane >> 4) * 16;
    const int b_row = wn * 32 + (lane & 7) + ((lane >> 4) & 1) * 8;
    const int b_kb  = ((lane >> 3) & 1) * 16;

    const __nv_bfloat16* opsA[2] = { Ah, Al };
    const __nv_bfloat16* opsB[2] = { Bh, Bl };
    const int boffA[2] = { SA_H, SA_L };
    const int boffB[2] = { SB_H, SB_L };

    const int lr = tid >> 3;
    const int lj = tid & 7;

    #define LOAD_STAGE(cc, ss) do {                                              \
        uint32_t stb = sb + (ss) * STAGE_BYTES;                                   \
        _Pragma("unroll")                                                         \
        for (int t = 0; t < 2; t++) {                                             \
            _Pragma("unroll")                                                     \
            for (int it = 0; it < 2; it++) {                                      \
                int r = lr + it * 32;                                             \
                int grow = row0 + r;                                              \
                uint32_t off = SW128((uint32_t)(r * 128 + lj * 16));              \
                cp_async16(stb + boffA[t] + off,                                  \
                           opsA[t] + (size_t)grow * F + (cc) * 64 + lj * 8,       \
                           grow < M);                                             \
            }                                                                     \
        }                                                                         \
        _Pragma("unroll")                                                         \
        for (int t = 0; t < 2; t++) {                                             \
            _Pragma("unroll")                                                     \
            for (int it = 0; it < 4; it++) {                                      \
                int r = lr + it * 32;                                             \
                uint32_t off = SW128((uint32_t)(r * 128 + lj * 16));              \
                cp_async16(stb + boffB[t] + off,                                  \
                           opsB[t] + (size_t)(col0 + r) * F + (cc) * 64 + lj * 8, \
                           true);                                                 \
            }                                                                     \
        }                                                                         \
        CP_COMMIT();                                                              \
    } while (0)

    uint32_t ah[2][2][4], al[2][2][4];
    uint32_t bh[2][2][4], bl[2][2][4];

    #define LDFRAGS(stb, ks, q) do {                                              \
        _Pragma("unroll")                                                         \
        for (int mt = 0; mt < 2; mt++) {                                          \
            uint32_t off = SW128((uint32_t)((a_row + mt * 16) * 128 + (ks) * 32 + a_kb)); \
            ldsm_x4(ah[q][mt], (stb) + SA_H + off);                               \
            ldsm_x4(al[q][mt], (stb) + SA_L + off);                               \
        }                                                                         \
        _Pragma("unroll")                                                         \
        for (int ntp = 0; ntp < 2; ntp++) {                                       \
            uint32_t off = SW128((uint32_t)((b_row + ntp * 16) * 128 + (ks) * 32 + b_kb)); \
            ldsm_x4(bh[q][ntp], (stb) + SB_H + off);                              \
            ldsm_x4(bl[q][ntp], (stb) + SB_L + off);                              \
        }                                                                         \
    } while (0)

    LOAD_STAGE(0, 0);

    #pragma unroll
    for (int c = 0; c < 4; c++) {
        CP_WAIT(0);
        __syncthreads();
        if (c + 1 < 4) LOAD_STAGE(c + 1, (c + 1) & 1);
        uint32_t stb = sb + (c & 1) * STAGE_BYTES;
        LDFRAGS(stb, 0, 0);
        #pragma unroll
        for (int ks = 0; ks < 4; ks++) {
            if (ks + 1 < 4) LDFRAGS(stb, ks + 1, (ks + 1) & 1);
            const int q = ks & 1;
            #pragma unroll
            for (int mt = 0; mt < 2; mt++)
                #pragma unroll
                for (int n8 = 0; n8 < 4; n8++) {
                    const uint32_t* bhf = &bh[q][n8 >> 1][(n8 & 1) * 2];
                    const uint32_t* blf = &bl[q][n8 >> 1][(n8 & 1) * 2];
                    mma16816(acc[mt][n8], ah[q][mt], bhf);
                    mma16816(acc[mt][n8], ah[q][mt], blf);
                    mma16816(acc[mt][n8], al[q][mt], bhf);
                }
        }
    }
    #undef LOAD_STAGE
    #undef LDFRAGS

    // ---- epilogue ----
    #pragma unroll
    for (int mt = 0; mt < 2; mt++) {
        #pragma unroll
        for (int half = 0; half < 2; half++) {
            int gr = row0 + wm * 32 + mt * 16 + (lane >> 2) + half * 8;
            bool rowok = gr < M;
            float ps = 0.f, pd = 0.f;
            #pragma unroll
            for (int n8 = 0; n8 < 4; n8++) {
                int gc = col0 + wn * 32 + n8 * 8 + (lane & 3) * 2;
                float v0 = acc[mt][n8][half * 2 + 0];
                float v1 = acc[mt][n8][half * 2 + 1];
                if (bias) { v0 += __ldg(bias + gc); v1 += __ldg(bias + gc + 1); }
                if (rowok) {
                    size_t base = (size_t)gr * F + gc;
                    if (out_h)
                        *reinterpret_cast<__half2*>(out_h + base) = __floats2half2_rn(v0, v1);
                    if (write_splitT) {   // transposed store into Wc slot [n][k]
                        __nv_bfloat16 h0 = __float2bfloat16(v0);
                        __nv_bfloat16 h1 = __float2bfloat16(v1);
                        g_Wh[0][(size_t)gc * F + gr] = h0;
                        g_Wl[0][(size_t)gc * F + gr] =
                            __float2bfloat16(v0 - __bfloat162float(h0));
                        g_Wh[0][(size_t)(gc + 1) * F + gr] = h1;
                        g_Wl[0][(size_t)(gc + 1) * F + gr] =
                            __float2bfloat16(v1 - __bfloat162float(h1));
                    }
                    if (a_src) {
                        ps += v0 * __ldg(a_src + gc) + v1 * __ldg(a_src + gc + 1);
                        pd += v0 * __ldg(a_dst + gc) + v1 * __ldg(a_dst + gc + 1);
                    }
                }
            }
            if (a_src) {
                ps += __shfl_xor_sync(0xffffffffu, ps, 1);
                ps += __shfl_xor_sync(0xffffffffu, ps, 2);
                pd += __shfl_xor_sync(0xffffffffu, pd, 1);
                pd += __shfl_xor_sync(0xffffffffu, pd, 2);
                if (rowok && (lane & 3) == 0) {
                    atomicAdd(&als[gr], ps);
                    atomicAdd(&ald[gr], pd);
                }
            }
        }
    }
}

// ---------------- GAT aggregation: warp per destination node ----------------
// fp16 feature gather; per-edge src+weight held in registers, shfl-broadcast
// into a zero-load inner loop. Each lane owns features [lane*8, lane*8+8).
__global__ void aggregate_kernel(const __half* __restrict__ hH,
                                 const float* __restrict__ bias,
                                 const float* __restrict__ als,
                                 const float* __restrict__ ald_arr,
                                 float* __restrict__ out, int write_split) {
    int node = (blockIdx.x * blockDim.x + threadIdx.x) >> 5;
    int lane = threadIdx.x & 31;
    if (node >= N_NODES) return;
    int beg = node * SLOT_CAP;
    int deg = g_deg[node];
    float ald = ald_arr[node];

    // scalar pass: each lane owns edges lane+32k (k<4); keep src + e in regs
    float el[4];
    int   sl[4];
    float m = -INFINITY;
    #pragma unroll
    for (int k = 0; k < 4; k++) {
        int idx = lane + k * 32;
        if (idx < deg) {
            int s0 = g_srcs[beg + idx];
            sl[k] = s0;
            float e = als[s0] + ald;
            e = (e > 0.f) ? e : NEG_SLOPE * e;
            el[k] = e;
            m = fmaxf(m, e);
        } else { sl[k] = 0; el[k] = -INFINITY; }
    }
    #pragma unroll
    for (int o = 16; o > 0; o >>= 1) m = fmaxf(m, __shfl_xor_sync(0xffffffffu, m, o));
    float wl[4];
    float s = 0.f;
    #pragma unroll
    for (int k = 0; k < 4; k++) {
        float w = (el[k] == -INFINITY) ? 0.f : __expf(el[k] - m);
        wl[k] = w;
        s += w;
    }
    #pragma unroll
    for (int o = 16; o > 0; o >>= 1) s += __shfl_xor_sync(0xffffffffu, s, o);
    float inv = 1.f / (s + EPS_F);

    // feature pass: zero-load inner loop (shfl src + weight, LDG.128, 8 FMA)
    float4 acc0 = make_float4(0.f, 0.f, 0.f, 0.f);
    float4 acc1 = make_float4(0.f, 0.f, 0.f, 0.f);
    #pragma unroll
    for (int k = 0; k < 4; k++) {
        int base_j = k * 32;
        if (base_j >= deg) break;
        int cnt = min(32, deg - base_j);
        for (int t = 0; t < cnt; t++) {
            float w   = __shfl_sync(0xffffffffu, wl[k], t);
            int   src = __shfl_sync(0xffffffffu, sl[k], t);
            uint4 v = __ldg(reinterpret_cast<const uint4*>(hH + (size_t)src * F) + lane);
            const __half2* hp = reinterpret_cast<const __half2*>(&v);
            float2 f0 = __half22float2(hp[0]);
            float2 f1 = __half22float2(hp[1]);
            float2 f2 = __half22float2(hp[2]);
            float2 f3 = __half22float2(hp[3]);
            acc0.x = fmaf(w, f0.x, acc0.x); acc0.y = fmaf(w, f0.y, acc0.y);
            acc0.z = fmaf(w, f1.x, acc0.z); acc0.w = fmaf(w, f1.y, acc0.w);
            acc1.x = fmaf(w, f2.x, acc1.x); acc1.y = fmaf(w, f2.y, acc1.y);
            acc1.z = fmaf(w, f3.x, acc1.z); acc1.w = fmaf(w, f3.y, acc1.w);
        }
    }

    // lane's 8 contiguous features: base = node*F + lane*8
    size_t base = (size_t)node * F + (size_t)lane * 8;
    const float* bp = bias + lane * 8;
    float4 r0 = make_float4(acc0.x * inv + __ldg(bp + 0), acc0.y * inv + __ldg(bp + 1),
                            acc0.z * inv + __ldg(bp + 2), acc0.w * inv + __ldg(bp + 3));
    float4 r1 = make_float4(acc1.x * inv + __ldg(bp + 4), acc1.y * inv + __ldg(bp + 5),
                            acc1.z * inv + __ldg(bp + 6), acc1.w * inv + __ldg(bp + 7));
    if (out) {
        *reinterpret_cast<float4*>(out + base)     = r0;
        *reinterpret_cast<float4*>(out + base + 4) = r1;
    }
    if (write_split) {
        __nv_bfloat16 h0 = __float2bfloat16(r0.x), h1 = __float2bfloat16(r0.y);
        __nv_bfloat16 h2 = __float2bfloat16(r0.z), h3 = __float2bfloat16(r0.w);
        __nv_bfloat16 h4 = __float2bfloat16(r1.x), h5 = __float2bfloat16(r1.y);
        __nv_bfloat16 h6 = __float2bfloat16(r1.z), h7 = __float2bfloat16(r1.w);
        __nv_bfloat162 hh[4] = {
            __nv_bfloat162(h0, h1), __nv_bfloat162(h2, h3),
            __nv_bfloat162(h4, h5), __nv_bfloat162(h6, h7) };
        __nv_bfloat162 ll[4] = {
            __nv_bfloat162(__float2bfloat16(r0.x - __bfloat162float(h0)),
                           __float2bfloat16(r0.y - __bfloat162float(h1))),
            __nv_bfloat162(__float2bfloat16(r0.z - __bfloat162float(h2)),
                           __float2bfloat16(r0.w - __bfloat162float(h3))),
            __nv_bfloat162(__float2bfloat16(r1.x - __bfloat162float(h4)),
                           __float2bfloat16(r1.y - __bfloat162float(h5))),
            __nv_bfloat162(__float2bfloat16(r1.z - __bfloat162float(h6)),
                           __float2bfloat16(r1.w - __bfloat162float(h7))) };
        *reinterpret_cast<uint4*>(g_Ah + base) = *reinterpret_cast<uint4*>(hh);
        *reinterpret_cast<uint4*>(g_Al + base) = *reinterpret_cast<uint4*>(ll);
    }
}

// ---------------- eval-edge dot products + state restore ----------------
#define DOT_B ((E_EVAL * 32 + 255) / 256)     // 12500
#define CLEAN_ELEMS (5 * N_NODES + F)         // deg + 4 al arrays + bc
#define CLEAN_B ((CLEAN_ELEMS + 2047) / 2048) // 25
__global__ void dot_kernel(const float* __restrict__ h,
                           const int* __restrict__ ei,
                           float* __restrict__ out) {
    int b = blockIdx.x;
    if (b >= DOT_B) {
        int base = (b - DOT_B) * 2048 + threadIdx.x;
        #pragma unroll
        for (int q = 0; q < 8; q++) {
            int i = base + q * 256;
            if (i < N_NODES) g_deg[i] = 0;
            else if (i < 2 * N_NODES) g_als1[i - N_NODES] = 0.f;
            else if (i < 3 * N_NODES) g_ald1[i - 2 * N_NODES] = 0.f;
            else if (i < 4 * N_NODES) g_als2[i - 3 * N_NODES] = 0.f;
            else if (i < 5 * N_NODES) g_ald2[i - 4 * N_NODES] = 0.f;
            else if (i < 5 * N_NODES + F) g_bc[i - 5 * N_NODES] = 0.f;
        }
        return;
    }
    int eid = (b * blockDim.x + threadIdx.x) >> 5;
    int lane = threadIdx.x & 31;
    if (eid >= E_EVAL) return;
    int a = ei[eid];
    int bb = ei[E_EVAL + eid];
    const float4* ha = reinterpret_cast<const float4*>(h + (size_t)a * F);
    const float4* hb = reinterpret_cast<const float4*>(h + (size_t)bb * F);
    float s = 0.f;
    #pragma unroll
    for (int k = 0; k < 2; k++) {
        float4 va = __ldg(ha + lane + k * 32);
        float4 vb = __ldg(hb + lane + k * 32);
        s = fmaf(va.x, vb.x, s);
        s = fmaf(va.y, vb.y, s);
        s = fmaf(va.z, vb.z, s);
        s = fmaf(va.w, vb.w, s);
    }
    #pragma unroll
    for (int o = 16; o > 0; o >>= 1) s += __shfl_xor_sync(0xffffffffu, s, o);
    if (lane == 0) out[eid] = s;
}

// ---------------- launch ----------------
extern "C" void kernel_launch(void* const* d_in, const int* in_sizes, int n_in,
                              void* d_out, int out_size) {
    const float* x       = (const float*)d_in[0];
    const int*   pos_ei  = (const int*)  d_in[1];
    const int*   ev_ei   = (const int*)  d_in[2];
    const float* Win_W   = (const float*)d_in[3];
    const float* Win_b   = (const float*)d_in[4];
    const float* W1      = (const float*)d_in[5];
    const float* a1_src  = (const float*)d_in[6];
    const float* a1_dst  = (const float*)d_in[7];
    const float* b1      = (const float*)d_in[8];
    const float* W2      = (const float*)d_in[9];
    const float* a2_src  = (const float*)d_in[10];
    const float* a2_dst  = (const float*)d_in[11];
    const float* b2      = (const float*)d_in[12];
    float* out = (float*)d_out;

    float *pB, *pAls1, *pAld1, *pAls2, *pAld2, *pBc;
    __half *pH;
    __nv_bfloat16 *pAh, *pAl, *pXh, *pXl, *pW1h, *pW1l, *pWh, *pWl;
    cudaGetSymbolAddress((void**)&pB, g_bufB);
    cudaGetSymbolAddress((void**)&pH, g_bufH);
    cudaGetSymbolAddress((void**)&pAls1, g_als1);
    cudaGetSymbolAddress((void**)&pAld1, g_ald1);
    cudaGetSymbolAddress((void**)&pAls2, g_als2);
    cudaGetSymbolAddress((void**)&pAld2, g_ald2);
    cudaGetSymbolAddress((void**)&pBc, g_bc);
    cudaGetSymbolAddress((void**)&pAh, g_Ah);
    cudaGetSymbolAddress((void**)&pAl, g_Al);
    cudaGetSymbolAddress((void**)&pXh, g_Xh);
    cudaGetSymbolAddress((void**)&pXl, g_Xl);
    cudaGetSymbolAddress((void**)&pW1h, g_W1h);
    cudaGetSymbolAddress((void**)&pW1l, g_W1l);
    cudaGetSymbolAddress((void**)&pWh, g_Wh);
    cudaGetSymbolAddress((void**)&pWl, g_Wl);

    cudaFuncSetAttribute(gemm_mma_kernel,
                         cudaFuncAttributeMaxDynamicSharedMemorySize, SMEM_MMA);

    const dim3 ggrid(2, (N_NODES + 63) / 64);
    const dim3 fgrid(2, F / 64);     // fold gemm: M=256 -> 8 CTAs
    const int warps_blocks_n = (N_NODES * 32 + 255) / 256;

    // fused: scatter + split(x, WinW, W1, W2) + fold_bias (state pre-zeroed)
    work_kernel<<<WORK_B, 256>>>(pos_ei, x, Win_W, W1, W2, Win_b);

    // fold gemm: Wc = Win_W @ W1 -> transposed split into g_Wh[0]/g_Wl[0]
    gemm_mma_kernel<<<fgrid, 256, SMEM_MMA>>>(
        pXh, pXl, pW1h, pW1l, nullptr,
        nullptr, nullptr, nullptr, nullptr,
        nullptr, 1, F);

    // gemm1: hW1 = x @ Wc + bc -> fp16 pH + fused al1
    gemm_mma_kernel<<<ggrid, 256, SMEM_MMA>>>(
        pAh, pAl, pWh + 0 * F * F, pWl + 0 * F * F, pBc,
        a1_src, a1_dst, pAls1, pAld1, pH, 0, N_NODES);
    // aggregate layer1 (fp16 gather) -> bf16 split for gemm2
    aggregate_kernel<<<warps_blocks_n, 256>>>(pH, b1, pAls1, pAld1, nullptr, 1);

    // gemm2: hW2 = h1 @ W2 -> fp16 pH + fused al2
    gemm_mma_kernel<<<ggrid, 256, SMEM_MMA>>>(
        pAh, pAl, pWh + 1 * F * F, pWl + 1 * F * F, nullptr,
        a2_src, a2_dst, pAls2, pAld2, pH, 0, N_NODES);
    // aggregate layer2 (fp16 gather) -> fp32 pB for dot
    aggregate_kernel<<<warps_blocks_n, 256>>>(pH, b2, pAls2, pAld2, pB, 0);

    // eval logits + state restore (extra cleanup blocks run concurrently)
    dot_kernel<<<DOT_B + CLEAN_B, 256>>>(pB, ev_ei, out);
}

// round 15
// speedup vs baseline: 1.2138x; 1.0223x over previous
#include <cuda_runtime.h>
#include <cuda_bf16.h>
#include <cuda_fp16.h>
#include <cstdint>
#include <math.h>

#define N_NODES 10000
#define F 256
#define E_POS 320000
#define E_TOT 330000
#define E_EVAL 100000
#define NEG_SLOPE 0.2f
#define EPS_F 1e-16f
#define SLOT_CAP 128

// ---------------- scratch (device globals; zero-initialized at load) ----------------
// g_deg / g_als* / g_ald* / g_bc rely on zero-init for the FIRST call and are
// re-zeroed at the tail of dot_kernel so every call sees identical state.
__device__ __half g_hOut[N_NODES * F];    // aggregate2 out (final h, fp16 for dot)
__device__ __half g_bufH[N_NODES * F];    // gemm fp16 out (aggregate gather source)
__device__ float g_als1[N_NODES];
__device__ float g_ald1[N_NODES];
__device__ float g_als2[N_NODES];
__device__ float g_ald2[N_NODES];
__device__ float g_bc[F];                 // folded bias Win_b @ W1
__device__ int   g_deg[N_NODES];
__device__ int   g_srcs[N_NODES * SLOT_CAP];
__device__ __nv_bfloat16 g_Ah[N_NODES * F];      // node features split (A operand)
__device__ __nv_bfloat16 g_Al[N_NODES * F];
__device__ __nv_bfloat16 g_Xh[F * F];            // Win_W split, row-major [m][k]
__device__ __nv_bfloat16 g_Xl[F * F];
__device__ __nv_bfloat16 g_W1h[F * F];           // W1 split, transposed [n][k]
__device__ __nv_bfloat16 g_W1l[F * F];
__device__ __nv_bfloat16 g_Wh[2][F * F];         // 0: Wc (fold result), 1: W2 — [n][k]
__device__ __nv_bfloat16 g_Wl[2][F * F];

#define SW128(o) ((o) ^ (((o) >> 3) & 0x70))

__device__ __forceinline__ uint32_t smem_to_u32(const void* p) {
    uint32_t a;
    asm("{ .reg .u64 t; cvta.to.shared.u64 t, %1; cvt.u32.u64 %0, t; }"
        : "=r"(a) : "l"(p));
    return a;
}
__device__ __forceinline__ void ldsm_x4(uint32_t* r, uint32_t addr) {
    asm volatile("ldmatrix.sync.aligned.m8n8.x4.shared.b16 {%0,%1,%2,%3}, [%4];"
        : "=r"(r[0]), "=r"(r[1]), "=r"(r[2]), "=r"(r[3]) : "r"(addr));
}
__device__ __forceinline__ void mma16816(float* c, const uint32_t* a, const uint32_t* b) {
    asm volatile(
        "mma.sync.aligned.m16n8k16.row.col.f32.bf16.bf16.f32 "
        "{%0,%1,%2,%3}, {%4,%5,%6,%7}, {%8,%9}, {%0,%1,%2,%3};"
        : "+f"(c[0]), "+f"(c[1]), "+f"(c[2]), "+f"(c[3])
        : "r"(a[0]), "r"(a[1]), "r"(a[2]), "r"(a[3]), "r"(b[0]), "r"(b[1]));
}
__device__ __forceinline__ void cp_async16(uint32_t saddr, const void* g, bool valid) {
    int sz = valid ? 16 : 0;
    asm volatile("cp.async.cg.shared.global [%0], [%1], 16, %2;"
        :: "r"(saddr), "l"(g), "r"(sz) : "memory");
}
#define CP_COMMIT() asm volatile("cp.async.commit_group;" ::: "memory")
#define CP_WAIT(n)  asm volatile("cp.async.wait_group %0;" :: "n"(n) : "memory")

// ---------------- fused independent work: scatter + split + fold_bias ----------------
#define E_Q (E_TOT / 4)                          // 82500
#define SC_B ((E_Q + 255) / 256)                 // 323
#define M4_A (N_NODES * F / 4)                   // 640000
#define SP_B ((M4_A + 3 * F * F + 255) / 256)
#define FB_B (F / 32)                            // 8
#define WORK_B (SC_B + SP_B + FB_B)

__global__ void work_kernel(const int* __restrict__ pos_ei,
                            const float* __restrict__ x,
                            const float* __restrict__ WinW,
                            const float* __restrict__ W1,
                            const float* __restrict__ W2,
                            const float* __restrict__ Win_b) {
    int b = blockIdx.x;
    if (b < SC_B) {
        int gid = b * blockDim.x + threadIdx.x;
        if (gid >= E_Q) return;
        #pragma unroll
        for (int q = 0; q < 4; q++) {
            int e = gid + q * E_Q;
            int src, dst;
            if (e < E_POS) { src = __ldg(pos_ei + e); dst = __ldg(pos_ei + E_POS + e); }
            else           { src = e - E_POS; dst = src; }
            int pos = atomicAdd(&g_deg[dst], 1);
            if (pos < SLOT_CAP) g_srcs[dst * SLOT_CAP + pos] = src;
        }
    } else if (b < SC_B + SP_B) {
        int idx = (b - SC_B) * blockDim.x + threadIdx.x;
        if (idx < M4_A) {
            float4 v = reinterpret_cast<const float4*>(x)[idx];
            __nv_bfloat16 h0 = __float2bfloat16(v.x), h1 = __float2bfloat16(v.y);
            __nv_bfloat16 h2 = __float2bfloat16(v.z), h3 = __float2bfloat16(v.w);
            __nv_bfloat16 l0 = __float2bfloat16(v.x - __bfloat162float(h0));
            __nv_bfloat16 l1 = __float2bfloat16(v.y - __bfloat162float(h1));
            __nv_bfloat16 l2 = __float2bfloat16(v.z - __bfloat162float(h2));
            __nv_bfloat16 l3 = __float2bfloat16(v.w - __bfloat162float(h3));
            __nv_bfloat162* ph = reinterpret_cast<__nv_bfloat162*>(g_Ah);
            __nv_bfloat162* pl = reinterpret_cast<__nv_bfloat162*>(g_Al);
            ph[idx * 2]     = __nv_bfloat162(h0, h1);
            ph[idx * 2 + 1] = __nv_bfloat162(h2, h3);
            pl[idx * 2]     = __nv_bfloat162(l0, l1);
            pl[idx * 2 + 1] = __nv_bfloat162(l2, l3);
        } else {
            int i2 = idx - M4_A;
            if (i2 < 3 * F * F) {
                int w = i2 >> 16;
                int j = i2 & 65535;
                int k = j >> 8, n = j & 255;
                if (w == 0) {
                    float v = __ldg(WinW + j);
                    __nv_bfloat16 h = __float2bfloat16(v);
                    g_Xh[j] = h;
                    g_Xl[j] = __float2bfloat16(v - __bfloat162float(h));
                } else if (w == 1) {
                    float v = __ldg(W1 + j);
                    __nv_bfloat16 h = __float2bfloat16(v);
                    g_W1h[n * F + k] = h;
                    g_W1l[n * F + k] = __float2bfloat16(v - __bfloat162float(h));
                } else {
                    float v = __ldg(W2 + j);
                    __nv_bfloat16 h = __float2bfloat16(v);
                    g_Wh[1][n * F + k] = h;
                    g_Wl[1][n * F + k] = __float2bfloat16(v - __bfloat162float(h));
                }
            }
        }
    } else {
        int n = threadIdx.x;
        int k0 = (b - SC_B - SP_B) * 32;
        float s = 0.f;
        #pragma unroll
        for (int kk = 0; kk < 32; kk++) {
            int k = k0 + kk;
            s = fmaf(__ldg(Win_b + k), __ldg(W1 + (size_t)k * F + n), s);
        }
        atomicAdd(&g_bc[n], s);
    }
}

// ---------------- pipelined HMMA GEMM ----------------
#define SA_H 0
#define SA_L 8192
#define SB_H 16384
#define SB_L 32768
#define STAGE_BYTES 49152
#define SMEM_MMA (2 * STAGE_BYTES + 1024)

__global__ __launch_bounds__(256, 2) void gemm_mma_kernel(
    const __nv_bfloat16* __restrict__ Ah, const __nv_bfloat16* __restrict__ Al,
    const __nv_bfloat16* __restrict__ Bh, const __nv_bfloat16* __restrict__ Bl,
    const float* __restrict__ bias,
    const float* __restrict__ a_src, const float* __restrict__ a_dst,
    float* __restrict__ als, float* __restrict__ ald,
    __half* __restrict__ out_h,
    int write_splitT, int M) {
    extern __shared__ char dsmem[];
    const int tid = threadIdx.x;
    const int wid = tid >> 5;
    const int lane = tid & 31;
    const int wm = wid >> 2;
    const int wn = wid & 3;
    const int row0 = blockIdx.y * 64;
    const int col0 = blockIdx.x * 128;

    uint32_t dsb = smem_to_u32(dsmem);
    uint32_t sb = (dsb + 1023) & ~1023u;

    float acc[2][4][4] = {};

    const int a_row = wm * 32 + (lane & 15);
    const int a_kb  = (lane >> 4) * 16;
    const int b_row = wn * 32 + (lane & 7) + ((lane >> 4) & 1) * 8;
    const int b_kb  = ((lane >> 3) & 1) * 16;

    const __nv_bfloat16* opsA[2] = { Ah, Al };
    const __nv_bfloat16* opsB[2] = { Bh, Bl };
    const int boffA[2] = { SA_H, SA_L };
    const int boffB[2] = { SB_H, SB_L };

    const int lr = tid >> 3;
    const int lj = tid & 7;

    #define LOAD_STAGE(cc, ss) do {                                              \
        uint32_t stb = sb + (ss) * STAGE_BYTES;                                   \
        _Pragma("unroll")                                                         \
        for (int t = 0; t < 2; t++) {                                             \
            _Pragma("unroll")                                                     \
            for (int it = 0; it < 2; it++) {                                      \
                int r = lr + it * 32;                                             \
                int grow = row0 + r;                                              \
                uint32_t off = SW128((uint32_t)(r * 128 + lj * 16));              \
                cp_async16(stb + boffA[t] + off,                                  \
                           opsA[t] + (size_t)grow * F + (cc) * 64 + lj * 8,       \
                           grow < M);                                             \
            }                                                                     \
        }                                                                         \
        _Pragma("unroll")                                                         \
        for (int t = 0; t < 2; t++) {                                             \
            _Pragma("unroll")                                                     \
            for (int it = 0; it < 4; it++) {                                      \
                int r = lr + it * 32;                                             \
                uint32_t off = SW128((uint32_t)(r * 128 + lj * 16));              \
                cp_async16(stb + boffB[t] + off,                                  \
                           opsB[t] + (size_t)(col0 + r) * F + (cc) * 64 + lj * 8, \
                           true);                                                 \
            }                                                                     \
        }                                                                         \
        CP_COMMIT();                                                              \
    } while (0)

    uint32_t ah[2][2][4], al[2][2][4];
    uint32_t bh[2][2][4], bl[2][2][4];

    #define LDFRAGS(stb, ks, q) do {                                              \
        _Pragma("unroll")                                                         \
        for (int mt = 0; mt < 2; mt++) {                                          \
            uint32_t off = SW128((uint32_t)((a_row + mt * 16) * 128 + (ks) * 32 + a_kb)); \
            ldsm_x4(ah[q][mt], (stb) + SA_H + off);                               \
            ldsm_x4(al[q][mt], (stb) + SA_L + off);                               \
        }                                                                         \
        _Pragma("unroll")                                                         \
        for (int ntp = 0; ntp < 2; ntp++) {                                       \
            uint32_t off = SW128((uint32_t)((b_row + ntp * 16) * 128 + (ks) * 32 + b_kb)); \
            ldsm_x4(bh[q][ntp], (stb) + SB_H + off);                              \
            ldsm_x4(bl[q][ntp], (stb) + SB_L + off);                              \
        }                                                                         \
    } while (0)

    LOAD_STAGE(0, 0);

    #pragma unroll
    for (int c = 0; c < 4; c++) {
        CP_WAIT(0);
        __syncthreads();
        if (c + 1 < 4) LOAD_STAGE(c + 1, (c + 1) & 1);
        uint32_t stb = sb + (c & 1) * STAGE_BYTES;
        LDFRAGS(stb, 0, 0);
        #pragma unroll
        for (int ks = 0; ks < 4; ks++) {
            if (ks + 1 < 4) LDFRAGS(stb, ks + 1, (ks + 1) & 1);
            const int q = ks & 1;
            #pragma unroll
            for (int mt = 0; mt < 2; mt++)
                #pragma unroll
                for (int n8 = 0; n8 < 4; n8++) {
                    const uint32_t* bhf = &bh[q][n8 >> 1][(n8 & 1) * 2];
                    const uint32_t* blf = &bl[q][n8 >> 1][(n8 & 1) * 2];
                    mma16816(acc[mt][n8], ah[q][mt], bhf);
                    mma16816(acc[mt][n8], ah[q][mt], blf);
                    mma16816(acc[mt][n8], al[q][mt], bhf);
                }
        }
    }
    #undef LOAD_STAGE
    #undef LDFRAGS

    // ---- epilogue ----
    #pragma unroll
    for (int mt = 0; mt < 2; mt++) {
        #pragma unroll
        for (int half = 0; half < 2; half++) {
            int gr = row0 + wm * 32 + mt * 16 + (lane >> 2) + half * 8;
            bool rowok = gr < M;
            float ps = 0.f, pd = 0.f;
            #pragma unroll
            for (int n8 = 0; n8 < 4; n8++) {
                int gc = col0 + wn * 32 + n8 * 8 + (lane & 3) * 2;
                float v0 = acc[mt][n8][half * 2 + 0];
                float v1 = acc[mt][n8][half * 2 + 1];
                if (bias) { v0 += __ldg(bias + gc); v1 += __ldg(bias + gc + 1); }
                if (rowok) {
                    size_t base = (size_t)gr * F + gc;
                    if (out_h)
                        *reinterpret_cast<__half2*>(out_h + base) = __floats2half2_rn(v0, v1);
                    if (write_splitT) {   // transposed store into Wc slot [n][k]
                        __nv_bfloat16 h0 = __float2bfloat16(v0);
                        __nv_bfloat16 h1 = __float2bfloat16(v1);
                        g_Wh[0][(size_t)gc * F + gr] = h0;
                        g_Wl[0][(size_t)gc * F + gr] =
                            __float2bfloat16(v0 - __bfloat162float(h0));
                        g_Wh[0][(size_t)(gc + 1) * F + gr] = h1;
                        g_Wl[0][(size_t)(gc + 1) * F + gr] =
                            __float2bfloat16(v1 - __bfloat162float(h1));
                    }
                    if (a_src) {
                        ps += v0 * __ldg(a_src + gc) + v1 * __ldg(a_src + gc + 1);
                        pd += v0 * __ldg(a_dst + gc) + v1 * __ldg(a_dst + gc + 1);
                    }
                }
            }
            if (a_src) {
                ps += __shfl_xor_sync(0xffffffffu, ps, 1);
                ps += __shfl_xor_sync(0xffffffffu, ps, 2);
                pd += __shfl_xor_sync(0xffffffffu, pd, 1);
                pd += __shfl_xor_sync(0xffffffffu, pd, 2);
                if (rowok && (lane & 3) == 0) {
                    atomicAdd(&als[gr], ps);
                    atomicAdd(&ald[gr], pd);
                }
            }
        }
    }
}

// ---------------- GAT aggregation: warp per destination node ----------------
// fp16 feature gather; per-edge src+weight held in registers, shfl-broadcast
// into a zero-load inner loop. Each lane owns features [lane*8, lane*8+8).
// write_split -> bf16 hi/lo (layer 1); out_h -> fp16 final h (layer 2).
__global__ void aggregate_kernel(const __half* __restrict__ hH,
                                 const float* __restrict__ bias,
                                 const float* __restrict__ als,
                                 const float* __restrict__ ald_arr,
                                 __half* __restrict__ out_h, int write_split) {
    int node = (blockIdx.x * blockDim.x + threadIdx.x) >> 5;
    int lane = threadIdx.x & 31;
    if (node >= N_NODES) return;
    int beg = node * SLOT_CAP;
    int deg = g_deg[node];
    float ald = ald_arr[node];

    // scalar pass: each lane owns edges lane+32k (k<4); keep src + e in regs
    float el[4];
    int   sl[4];
    float m = -INFINITY;
    #pragma unroll
    for (int k = 0; k < 4; k++) {
        int idx = lane + k * 32;
        if (idx < deg) {
            int s0 = g_srcs[beg + idx];
            sl[k] = s0;
            float e = als[s0] + ald;
            e = (e > 0.f) ? e : NEG_SLOPE * e;
            el[k] = e;
            m = fmaxf(m, e);
        } else { sl[k] = 0; el[k] = -INFINITY; }
    }
    #pragma unroll
    for (int o = 16; o > 0; o >>= 1) m = fmaxf(m, __shfl_xor_sync(0xffffffffu, m, o));
    float wl[4];
    float s = 0.f;
    #pragma unroll
    for (int k = 0; k < 4; k++) {
        float w = (el[k] == -INFINITY) ? 0.f : __expf(el[k] - m);
        wl[k] = w;
        s += w;
    }
    #pragma unroll
    for (int o = 16; o > 0; o >>= 1) s += __shfl_xor_sync(0xffffffffu, s, o);
    float inv = 1.f / (s + EPS_F);

    // feature pass: zero-load inner loop (shfl src + weight, LDG.128, 8 FMA)
    float4 acc0 = make_float4(0.f, 0.f, 0.f, 0.f);
    float4 acc1 = make_float4(0.f, 0.f, 0.f, 0.f);
    #pragma unroll
    for (int k = 0; k < 4; k++) {
        int base_j = k * 32;
        if (base_j >= deg) break;
        int cnt = min(32, deg - base_j);
        for (int t = 0; t < cnt; t++) {
            float w   = __shfl_sync(0xffffffffu, wl[k], t);
            int   src = __shfl_sync(0xffffffffu, sl[k], t);
            uint4 v = __ldg(reinterpret_cast<const uint4*>(hH + (size_t)src * F) + lane);
            const __half2* hp = reinterpret_cast<const __half2*>(&v);
            float2 f0 = __half22float2(hp[0]);
            float2 f1 = __half22float2(hp[1]);
            float2 f2 = __half22float2(hp[2]);
            float2 f3 = __half22float2(hp[3]);
            acc0.x = fmaf(w, f0.x, acc0.x); acc0.y = fmaf(w, f0.y, acc0.y);
            acc0.z = fmaf(w, f1.x, acc0.z); acc0.w = fmaf(w, f1.y, acc0.w);
            acc1.x = fmaf(w, f2.x, acc1.x); acc1.y = fmaf(w, f2.y, acc1.y);
            acc1.z = fmaf(w, f3.x, acc1.z); acc1.w = fmaf(w, f3.y, acc1.w);
        }
    }

    // lane's 8 contiguous features: base = node*F + lane*8
    size_t base = (size_t)node * F + (size_t)lane * 8;
    const float* bp = bias + lane * 8;
    float4 r0 = make_float4(acc0.x * inv + __ldg(bp + 0), acc0.y * inv + __ldg(bp + 1),
                            acc0.z * inv + __ldg(bp + 2), acc0.w * inv + __ldg(bp + 3));
    float4 r1 = make_float4(acc1.x * inv + __ldg(bp + 4), acc1.y * inv + __ldg(bp + 5),
                            acc1.z * inv + __ldg(bp + 6), acc1.w * inv + __ldg(bp + 7));
    if (out_h) {
        __half2 oh[4] = {
            __floats2half2_rn(r0.x, r0.y), __floats2half2_rn(r0.z, r0.w),
            __floats2half2_rn(r1.x, r1.y), __floats2half2_rn(r1.z, r1.w) };
        *reinterpret_cast<uint4*>(out_h + base) = *reinterpret_cast<uint4*>(oh);
    }
    if (write_split) {
        __nv_bfloat16 h0 = __float2bfloat16(r0.x), h1 = __float2bfloat16(r0.y);
        __nv_bfloat16 h2 = __float2bfloat16(r0.z), h3 = __float2bfloat16(r0.w);
        __nv_bfloat16 h4 = __float2bfloat16(r1.x), h5 = __float2bfloat16(r1.y);
        __nv_bfloat16 h6 = __float2bfloat16(r1.z), h7 = __float2bfloat16(r1.w);
        __nv_bfloat162 hh[4] = {
            __nv_bfloat162(h0, h1), __nv_bfloat162(h2, h3),
            __nv_bfloat162(h4, h5), __nv_bfloat162(h6, h7) };
        __nv_bfloat162 ll[4] = {
            __nv_bfloat162(__float2bfloat16(r0.x - __bfloat162float(h0)),
                           __float2bfloat16(r0.y - __bfloat162float(h1))),
            __nv_bfloat162(__float2bfloat16(r0.z - __bfloat162float(h2)),
                           __float2bfloat16(r0.w - __bfloat162float(h3))),
            __nv_bfloat162(__float2bfloat16(r1.x - __bfloat162float(h4)),
                           __float2bfloat16(r1.y - __bfloat162float(h5))),
            __nv_bfloat162(__float2bfloat16(r1.z - __bfloat162float(h6)),
                           __float2bfloat16(r1.w - __bfloat162float(h7))) };
        *reinterpret_cast<uint4*>(g_Ah + base) = *reinterpret_cast<uint4*>(hh);
        *reinterpret_cast<uint4*>(g_Al + base) = *reinterpret_cast<uint4*>(ll);
    }
}

// ---------------- eval-edge dot products (fp16 inputs) + state restore ----------------
#define DOT_B ((E_EVAL * 32 + 255) / 256)     // 12500
#define CLEAN_ELEMS (5 * N_NODES + F)         // deg + 4 al arrays + bc
#define CLEAN_B ((CLEAN_ELEMS + 2047) / 2048) // 25
__global__ void dot_kernel(const __half* __restrict__ h,
                           const int* __restrict__ ei,
                           float* __restrict__ out) {
    int b = blockIdx.x;
    if (b >= DOT_B) {
        int base = (b - DOT_B) * 2048 + threadIdx.x;
        #pragma unroll
        for (int q = 0; q < 8; q++) {
            int i = base + q * 256;
            if (i < N_NODES) g_deg[i] = 0;
            else if (i < 2 * N_NODES) g_als1[i - N_NODES] = 0.f;
            else if (i < 3 * N_NODES) g_ald1[i - 2 * N_NODES] = 0.f;
            else if (i < 4 * N_NODES) g_als2[i - 3 * N_NODES] = 0.f;
            else if (i < 5 * N_NODES) g_ald2[i - 4 * N_NODES] = 0.f;
            else if (i < 5 * N_NODES + F) g_bc[i - 5 * N_NODES] = 0.f;
        }
        return;
    }
    int eid = (b * blockDim.x + threadIdx.x) >> 5;
    int lane = threadIdx.x & 31;
    if (eid >= E_EVAL) return;
    int a = ei[eid];
    int bb = ei[E_EVAL + eid];
    // each lane: 8 contiguous halves from each operand row (one LDG.128 each)
    uint4 va = __ldg(reinterpret_cast<const uint4*>(h + (size_t)a * F) + lane);
    uint4 vb = __ldg(reinterpret_cast<const uint4*>(h + (size_t)bb * F) + lane);
    const __half2* pa = reinterpret_cast<const __half2*>(&va);
    const __half2* pb = reinterpret_cast<const __half2*>(&vb);
    float s = 0.f;
    #pragma unroll
    for (int k = 0; k < 4; k++) {
        float2 fa = __half22float2(pa[k]);
        float2 fb = __half22float2(pb[k]);
        s = fmaf(fa.x, fb.x, s);
        s = fmaf(fa.y, fb.y, s);
    }
    #pragma unroll
    for (int o = 16; o > 0; o >>= 1) s += __shfl_xor_sync(0xffffffffu, s, o);
    if (lane == 0) out[eid] = s;
}

// ---------------- launch ----------------
extern "C" void kernel_launch(void* const* d_in, const int* in_sizes, int n_in,
                              void* d_out, int out_size) {
    const float* x       = (const float*)d_in[0];
    const int*   pos_ei  = (const int*)  d_in[1];
    const int*   ev_ei   = (const int*)  d_in[2];
    const float* Win_W   = (const float*)d_in[3];
    const float* Win_b   = (const float*)d_in[4];
    const float* W1      = (const float*)d_in[5];
    const float* a1_src  = (const float*)d_in[6];
    const float* a1_dst  = (const float*)d_in[7];
    const float* b1      = (const float*)d_in[8];
    const float* W2      = (const float*)d_in[9];
    const float* a2_src  = (const float*)d_in[10];
    const float* a2_dst  = (const float*)d_in[11];
    const float* b2      = (const float*)d_in[12];
    float* out = (float*)d_out;

    float *pAls1, *pAld1, *pAls2, *pAld2, *pBc;
    __half *pH, *pHO;
    __nv_bfloat16 *pAh, *pAl, *pXh, *pXl, *pW1h, *pW1l, *pWh, *pWl;
    cudaGetSymbolAddress((void**)&pHO, g_hOut);
    cudaGetSymbolAddress((void**)&pH, g_bufH);
    cudaGetSymbolAddress((void**)&pAls1, g_als1);
    cudaGetSymbolAddress((void**)&pAld1, g_ald1);
    cudaGetSymbolAddress((void**)&pAls2, g_als2);
    cudaGetSymbolAddress((void**)&pAld2, g_ald2);
    cudaGetSymbolAddress((void**)&pBc, g_bc);
    cudaGetSymbolAddress((void**)&pAh, g_Ah);
    cudaGetSymbolAddress((void**)&pAl, g_Al);
    cudaGetSymbolAddress((void**)&pXh, g_Xh);
    cudaGetSymbolAddress((void**)&pXl, g_Xl);
    cudaGetSymbolAddress((void**)&pW1h, g_W1h);
    cudaGetSymbolAddress((void**)&pW1l, g_W1l);
    cudaGetSymbolAddress((void**)&pWh, g_Wh);
    cudaGetSymbolAddress((void**)&pWl, g_Wl);

    cudaFuncSetAttribute(gemm_mma_kernel,
                         cudaFuncAttributeMaxDynamicSharedMemorySize, SMEM_MMA);

    const dim3 ggrid(2, (N_NODES + 63) / 64);
    const dim3 fgrid(2, F / 64);     // fold gemm: M=256 -> 8 CTAs
    const int warps_blocks_n = (N_NODES * 32 + 255) / 256;

    // fused: scatter + split(x, WinW, W1, W2) + fold_bias (state pre-zeroed)
    work_kernel<<<WORK_B, 256>>>(pos_ei, x, Win_W, W1, W2, Win_b);

    // fold gemm: Wc = Win_W @ W1 -> transposed split into g_Wh[0]/g_Wl[0]
    gemm_mma_kernel<<<fgrid, 256, SMEM_MMA>>>(
        pXh, pXl, pW1h, pW1l, nullptr,
        nullptr, nullptr, nullptr, nullptr,
        nullptr, 1, F);

    // gemm1: hW1 = x @ Wc + bc -> fp16 pH + fused al1
    gemm_mma_kernel<<<ggrid, 256, SMEM_MMA>>>(
        pAh, pAl, pWh + 0 * F * F, pWl + 0 * F * F, pBc,
        a1_src, a1_dst, pAls1, pAld1, pH, 0, N_NODES);
    // aggregate layer1 (fp16 gather) -> bf16 split for gemm2
    aggregate_kernel<<<warps_blocks_n, 256>>>(pH, b1, pAls1, pAld1, nullptr, 1);

    // gemm2: hW2 = h1 @ W2 -> fp16 pH + fused al2
    gemm_mma_kernel<<<ggrid, 256, SMEM_MMA>>>(
        pAh, pAl, pWh + 1 * F * F, pWl + 1 * F * F, nullptr,
        a2_src, a2_dst, pAls2, pAld2, pH, 0, N_NODES);
    // aggregate layer2 (fp16 gather) -> fp16 final h
    aggregate_kernel<<<warps_blocks_n, 256>>>(pH, b2, pAls2, pAld2, pHO, 0);

    // eval logits (fp16 inputs) + state restore (cleanup blocks run concurrently)
    dot_kernel<<<DOT_B + CLEAN_B, 256>>>(pHO, ev_ei, out);
}

// round 16
// speedup vs baseline: 1.4721x; 1.2127x over previous
#include <cuda_runtime.h>
#include <cuda_bf16.h>
#include <cuda_fp16.h>
#include <cstdint>
#include <math.h>

#define N_NODES 10000
#define F 256
#define E_POS 320000
#define E_TOT 330000
#define E_EVAL 100000
#define NEG_SLOPE 0.2f
#define EPS_F 1e-16f
#define SLOT_CAP 128

// ---------------- scratch (device globals; zero-initialized at load) ----------------
// g_deg / g_als* / g_ald* / g_bc rely on zero-init for the FIRST call and are
// re-zeroed at the tail of dot_kernel so every call sees identical state.
__device__ __half g_xH[N_NODES * F];      // x in fp16 (gemm1 A operand)
__device__ __half g_h1H[N_NODES * F];     // aggregate1 out (gemm2 A operand)
__device__ __half g_bufH[N_NODES * F];    // gemm fp16 out (aggregate gather source)
__device__ __half g_hOut[N_NODES * F];    // aggregate2 out (dot source)
__device__ float g_als1[N_NODES];
__device__ float g_ald1[N_NODES];
__device__ float g_als2[N_NODES];
__device__ float g_ald2[N_NODES];
__device__ float g_bc[F];                 // folded bias Win_b @ W1
__device__ int   g_deg[N_NODES];
__device__ int   g_srcs[N_NODES * SLOT_CAP];
__device__ __nv_bfloat16 g_Xh[F * F];     // Win_W split, row-major [m][k] (fold A)
__device__ __nv_bfloat16 g_Xl[F * F];
__device__ __nv_bfloat16 g_W1h[F * F];    // W1 split, transposed [n][k] (fold B)
__device__ __nv_bfloat16 g_W1l[F * F];
__device__ __half g_WcH[F * F];           // fold result Wc, fp16 [n][k]
__device__ __half g_W2H[F * F];           // W2, fp16 [n][k]

#define SW128(o) ((o) ^ (((o) >> 3) & 0x70))

__device__ __forceinline__ uint32_t smem_to_u32(const void* p) {
    uint32_t a;
    asm("{ .reg .u64 t; cvta.to.shared.u64 t, %1; cvt.u32.u64 %0, t; }"
        : "=r"(a) : "l"(p));
    return a;
}
__device__ __forceinline__ void ldsm_x4(uint32_t* r, uint32_t addr) {
    asm volatile("ldmatrix.sync.aligned.m8n8.x4.shared.b16 {%0,%1,%2,%3}, [%4];"
        : "=r"(r[0]), "=r"(r[1]), "=r"(r[2]), "=r"(r[3]) : "r"(addr));
}
__device__ __forceinline__ void mma_bf16(float* c, const uint32_t* a, const uint32_t* b) {
    asm volatile(
        "mma.sync.aligned.m16n8k16.row.col.f32.bf16.bf16.f32 "
        "{%0,%1,%2,%3}, {%4,%5,%6,%7}, {%8,%9}, {%0,%1,%2,%3};"
        : "+f"(c[0]), "+f"(c[1]), "+f"(c[2]), "+f"(c[3])
        : "r"(a[0]), "r"(a[1]), "r"(a[2]), "r"(a[3]), "r"(b[0]), "r"(b[1]));
}
__device__ __forceinline__ void mma_f16(float* c, const uint32_t* a, const uint32_t* b) {
    asm volatile(
        "mma.sync.aligned.m16n8k16.row.col.f32.f16.f16.f32 "
        "{%0,%1,%2,%3}, {%4,%5,%6,%7}, {%8,%9}, {%0,%1,%2,%3};"
        : "+f"(c[0]), "+f"(c[1]), "+f"(c[2]), "+f"(c[3])
        : "r"(a[0]), "r"(a[1]), "r"(a[2]), "r"(a[3]), "r"(b[0]), "r"(b[1]));
}
__device__ __forceinline__ void cp_async16(uint32_t saddr, const void* g, bool valid) {
    int sz = valid ? 16 : 0;
    asm volatile("cp.async.cg.shared.global [%0], [%1], 16, %2;"
        :: "r"(saddr), "l"(g), "r"(sz) : "memory");
}
#define CP_COMMIT() asm volatile("cp.async.commit_group;" ::: "memory")
#define CP_WAIT(n)  asm volatile("cp.async.wait_group %0;" :: "n"(n) : "memory")

// ---------------- fused independent work ----------------
#define E_Q (E_TOT / 4)                          // 82500
#define SC_B ((E_Q + 255) / 256)                 // 323
#define X16_N (N_NODES * F / 8)                  // 320000 (8 floats/thread)
#define SP_B ((X16_N + 3 * F * F + 255) / 256)
#define FB_B (F / 32)                            // 8
#define WORK_B (SC_B + SP_B + FB_B)

__global__ void work_kernel(const int* __restrict__ pos_ei,
                            const float* __restrict__ x,
                            const float* __restrict__ WinW,
                            const float* __restrict__ W1,
                            const float* __restrict__ W2,
                            const float* __restrict__ Win_b) {
    int b = blockIdx.x;
    if (b < SC_B) {
        int gid = b * blockDim.x + threadIdx.x;
        if (gid >= E_Q) return;
        #pragma unroll
        for (int q = 0; q < 4; q++) {
            int e = gid + q * E_Q;
            int src, dst;
            if (e < E_POS) { src = __ldg(pos_ei + e); dst = __ldg(pos_ei + E_POS + e); }
            else           { src = e - E_POS; dst = src; }
            int pos = atomicAdd(&g_deg[dst], 1);
            if (pos < SLOT_CAP) g_srcs[dst * SLOT_CAP + pos] = src;
        }
    } else if (b < SC_B + SP_B) {
        int idx = (b - SC_B) * blockDim.x + threadIdx.x;
        if (idx < X16_N) {
            // x -> fp16 (8 floats per thread)
            float4 v0 = reinterpret_cast<const float4*>(x)[idx * 2];
            float4 v1 = reinterpret_cast<const float4*>(x)[idx * 2 + 1];
            __half2 h[4] = {
                __floats2half2_rn(v0.x, v0.y), __floats2half2_rn(v0.z, v0.w),
                __floats2half2_rn(v1.x, v1.y), __floats2half2_rn(v1.z, v1.w) };
            reinterpret_cast<uint4*>(g_xH)[idx] = *reinterpret_cast<uint4*>(h);
        } else {
            int i2 = idx - X16_N;
            if (i2 < 3 * F * F) {
                int w = i2 >> 16;
                int j = i2 & 65535;
                int k = j >> 8, n = j & 255;
                if (w == 0) {
                    float v = __ldg(WinW + j);          // row-major A for fold
                    __nv_bfloat16 h = __float2bfloat16(v);
                    g_Xh[j] = h;
                    g_Xl[j] = __float2bfloat16(v - __bfloat162float(h));
                } else if (w == 1) {
                    float v = __ldg(W1 + j);            // [n][k] B for fold
                    __nv_bfloat16 h = __float2bfloat16(v);
                    g_W1h[n * F + k] = h;
                    g_W1l[n * F + k] = __float2bfloat16(v - __bfloat162float(h));
                } else {
                    g_W2H[n * F + k] = __float2half(__ldg(W2 + j));  // [n][k] fp16
                }
            }
        }
    } else {
        int n = threadIdx.x;
        int k0 = (b - SC_B - SP_B) * 32;
        float s = 0.f;
        #pragma unroll
        for (int kk = 0; kk < 32; kk++) {
            int k = k0 + kk;
            s = fmaf(__ldg(Win_b + k), __ldg(W1 + (size_t)k * F + n), s);
        }
        atomicAdd(&g_bc[n], s);
    }
}

// ---------------- fold GEMM (bf16 3-term, accuracy): Wc = Win_W @ W1 -> fp16 [n][k] ----------------
#define SA_H 0
#define SA_L 8192
#define SB_H 16384
#define SB_L 32768
#define STAGE_BYTES 49152
#define SMEM_FOLD (2 * STAGE_BYTES + 1024)

__global__ __launch_bounds__(256, 2) void gemm_fold_kernel(
    const __nv_bfloat16* __restrict__ Ah, const __nv_bfloat16* __restrict__ Al,
    const __nv_bfloat16* __restrict__ Bh, const __nv_bfloat16* __restrict__ Bl,
    int M) {
    extern __shared__ char dsmem[];
    const int tid = threadIdx.x;
    const int wid = tid >> 5;
    const int lane = tid & 31;
    const int wm = wid >> 2;
    const int wn = wid & 3;
    const int row0 = blockIdx.y * 64;
    const int col0 = blockIdx.x * 128;

    uint32_t dsb = smem_to_u32(dsmem);
    uint32_t sb = (dsb + 1023) & ~1023u;

    float acc[2][4][4] = {};

    const int a_row = wm * 32 + (lane & 15);
    const int a_kb  = (lane >> 4) * 16;
    const int b_row = wn * 32 + (lane & 7) + ((lane >> 4) & 1) * 8;
    const int b_kb  = ((lane >> 3) & 1) * 16;

    const __nv_bfloat16* opsA[2] = { Ah, Al };
    const __nv_bfloat16* opsB[2] = { Bh, Bl };
    const int boffA[2] = { SA_H, SA_L };
    const int boffB[2] = { SB_H, SB_L };

    const int lr = tid >> 3;
    const int lj = tid & 7;

    #define LOAD_STAGE_F(cc, ss) do {                                            \
        uint32_t stb = sb + (ss) * STAGE_BYTES;                                   \
        _Pragma("unroll")                                                         \
        for (int t = 0; t < 2; t++) {                                             \
            _Pragma("unroll")                                                     \
            for (int it = 0; it < 2; it++) {                                      \
                int r = lr + it * 32;                                             \
                int grow = row0 + r;                                              \
                uint32_t off = SW128((uint32_t)(r * 128 + lj * 16));              \
                cp_async16(stb + boffA[t] + off,                                  \
                           opsA[t] + (size_t)grow * F + (cc) * 64 + lj * 8,       \
                           grow < M);                                             \
            }                                                                     \
        }                                                                         \
        _Pragma("unroll")                                                         \
        for (int t = 0; t < 2; t++) {                                             \
            _Pragma("unroll")                                                     \
            for (int it = 0; it < 4; it++) {                                      \
                int r = lr + it * 32;                                             \
                uint32_t off = SW128((uint32_t)(r * 128 + lj * 16));              \
                cp_async16(stb + boffB[t] + off,                                  \
                           opsB[t] + (size_t)(col0 + r) * F + (cc) * 64 + lj * 8, \
                           true);                                                 \
            }                                                                     \
        }                                                                         \
        CP_COMMIT();                                                              \
    } while (0)

    LOAD_STAGE_F(0, 0);

    #pragma unroll
    for (int c = 0; c < 4; c++) {
        CP_WAIT(0);
        __syncthreads();
        if (c + 1 < 4) LOAD_STAGE_F(c + 1, (c + 1) & 1);
        uint32_t stb = sb + (c & 1) * STAGE_BYTES;
        #pragma unroll
        for (int ks = 0; ks < 4; ks++) {
            uint32_t ah[2][4], al[2][4], bh[2][4], bl[2][4];
            #pragma unroll
            for (int mt = 0; mt < 2; mt++) {
                uint32_t off = SW128((uint32_t)((a_row + mt * 16) * 128 + ks * 32 + a_kb));
                ldsm_x4(ah[mt], stb + SA_H + off);
                ldsm_x4(al[mt], stb + SA_L + off);
            }
            #pragma unroll
            for (int ntp = 0; ntp < 2; ntp++) {
                uint32_t off = SW128((uint32_t)((b_row + ntp * 16) * 128 + ks * 32 + b_kb));
                ldsm_x4(bh[ntp], stb + SB_H + off);
                ldsm_x4(bl[ntp], stb + SB_L + off);
            }
            #pragma unroll
            for (int mt = 0; mt < 2; mt++)
                #pragma unroll
                for (int n8 = 0; n8 < 4; n8++) {
                    const uint32_t* bhf = &bh[n8 >> 1][(n8 & 1) * 2];
                    const uint32_t* blf = &bl[n8 >> 1][(n8 & 1) * 2];
                    mma_bf16(acc[mt][n8], ah[mt], bhf);
                    mma_bf16(acc[mt][n8], ah[mt], blf);
                    mma_bf16(acc[mt][n8], al[mt], bhf);
                }
        }
        __syncthreads();
    }
    #undef LOAD_STAGE_F

    // transposed fp16 store into Wc [n][k]
    #pragma unroll
    for (int mt = 0; mt < 2; mt++) {
        #pragma unroll
        for (int half = 0; half < 2; half++) {
            int gr = row0 + wm * 32 + mt * 16 + (lane >> 2) + half * 8;
            if (gr >= M) continue;
            #pragma unroll
            for (int n8 = 0; n8 < 4; n8++) {
                int gc = col0 + wn * 32 + n8 * 8 + (lane & 3) * 2;
                g_WcH[(size_t)gc * F + gr]       = __float2half(acc[mt][n8][half * 2 + 0]);
                g_WcH[(size_t)(gc + 1) * F + gr] = __float2half(acc[mt][n8][half * 2 + 1]);
            }
        }
    }
}

// ---------------- single-term fp16 GEMM ----------------
// BM=64 BN=128 BK=64; A tile 8KB, B tile 16KB; stage 24KB, double buffered
#define G16_SA 0
#define G16_SB 8192
#define G16_STAGE 24576
#define SMEM_G16 (2 * G16_STAGE + 1024)

__global__ __launch_bounds__(256, 2) void gemm16_kernel(
    const __half* __restrict__ A, const __half* __restrict__ B,
    const float* __restrict__ bias,
    const float* __restrict__ a_src, const float* __restrict__ a_dst,
    float* __restrict__ als, float* __restrict__ ald,
    __half* __restrict__ out_h, int M) {
    extern __shared__ char dsmem[];
    const int tid = threadIdx.x;
    const int wid = tid >> 5;
    const int lane = tid & 31;
    const int wm = wid >> 2;
    const int wn = wid & 3;
    const int row0 = blockIdx.y * 64;
    const int col0 = blockIdx.x * 128;

    uint32_t dsb = smem_to_u32(dsmem);
    uint32_t sb = (dsb + 1023) & ~1023u;

    float acc[2][4][4] = {};

    const int a_row = wm * 32 + (lane & 15);
    const int a_kb  = (lane >> 4) * 16;
    const int b_row = wn * 32 + (lane & 7) + ((lane >> 4) & 1) * 8;
    const int b_kb  = ((lane >> 3) & 1) * 16;

    const int lr = tid >> 3;
    const int lj = tid & 7;

    #define LOAD_STAGE16(cc, ss) do {                                             \
        uint32_t stb = sb + (ss) * G16_STAGE;                                     \
        _Pragma("unroll")                                                         \
        for (int it = 0; it < 2; it++) {                                          \
            int r = lr + it * 32;                                                 \
            int grow = row0 + r;                                                  \
            uint32_t off = SW128((uint32_t)(r * 128 + lj * 16));                  \
            cp_async16(stb + G16_SA + off,                                        \
                       A + (size_t)grow * F + (cc) * 64 + lj * 8, grow < M);      \
        }                                                                         \
        _Pragma("unroll")                                                         \
        for (int it = 0; it < 4; it++) {                                          \
            int r = lr + it * 32;                                                 \
            uint32_t off = SW128((uint32_t)(r * 128 + lj * 16));                  \
            cp_async16(stb + G16_SB + off,                                        \
                       B + (size_t)(col0 + r) * F + (cc) * 64 + lj * 8, true);    \
        }                                                                         \
        CP_COMMIT();                                                              \
    } while (0)

    uint32_t ah[2][2][4], bh[2][2][4];

    #define LDFRAGS16(stb, ks, q) do {                                            \
        _Pragma("unroll")                                                         \
        for (int mt = 0; mt < 2; mt++) {                                          \
            uint32_t off = SW128((uint32_t)((a_row + mt * 16) * 128 + (ks) * 32 + a_kb)); \
            ldsm_x4(ah[q][mt], (stb) + G16_SA + off);                             \
        }                                                                         \
        _Pragma("unroll")                                                         \
        for (int ntp = 0; ntp < 2; ntp++) {                                       \
            uint32_t off = SW128((uint32_t)((b_row + ntp * 16) * 128 + (ks) * 32 + b_kb)); \
            ldsm_x4(bh[q][ntp], (stb) + G16_SB + off);                            \
        }                                                                         \
    } while (0)

    LOAD_STAGE16(0, 0);

    #pragma unroll
    for (int c = 0; c < 4; c++) {
        CP_WAIT(0);
        __syncthreads();
        if (c + 1 < 4) LOAD_STAGE16(c + 1, (c + 1) & 1);
        uint32_t stb = sb + (c & 1) * G16_STAGE;
        LDFRAGS16(stb, 0, 0);
        #pragma unroll
        for (int ks = 0; ks < 4; ks++) {
            if (ks + 1 < 4) LDFRAGS16(stb, ks + 1, (ks + 1) & 1);
            const int q = ks & 1;
            #pragma unroll
            for (int mt = 0; mt < 2; mt++)
                #pragma unroll
                for (int n8 = 0; n8 < 4; n8++)
                    mma_f16(acc[mt][n8], ah[q][mt], &bh[q][n8 >> 1][(n8 & 1) * 2]);
        }
    }
    #undef LOAD_STAGE16
    #undef LDFRAGS16

    // ---- epilogue ----
    #pragma unroll
    for (int mt = 0; mt < 2; mt++) {
        #pragma unroll
        for (int half = 0; half < 2; half++) {
            int gr = row0 + wm * 32 + mt * 16 + (lane >> 2) + half * 8;
            bool rowok = gr < M;
            float ps = 0.f, pd = 0.f;
            #pragma unroll
            for (int n8 = 0; n8 < 4; n8++) {
                int gc = col0 + wn * 32 + n8 * 8 + (lane & 3) * 2;
                float v0 = acc[mt][n8][half * 2 + 0];
                float v1 = acc[mt][n8][half * 2 + 1];
                if (bias) { v0 += __ldg(bias + gc); v1 += __ldg(bias + gc + 1); }
                if (rowok) {
                    size_t base = (size_t)gr * F + gc;
                    *reinterpret_cast<__half2*>(out_h + base) = __floats2half2_rn(v0, v1);
                    ps += v0 * __ldg(a_src + gc) + v1 * __ldg(a_src + gc + 1);
                    pd += v0 * __ldg(a_dst + gc) + v1 * __ldg(a_dst + gc + 1);
                }
            }
            ps += __shfl_xor_sync(0xffffffffu, ps, 1);
            ps += __shfl_xor_sync(0xffffffffu, ps, 2);
            pd += __shfl_xor_sync(0xffffffffu, pd, 1);
            pd += __shfl_xor_sync(0xffffffffu, pd, 2);
            if (rowok && (lane & 3) == 0) {
                atomicAdd(&als[gr], ps);
                atomicAdd(&ald[gr], pd);
            }
        }
    }
}

// ---------------- GAT aggregation: warp per destination node ----------------
__global__ void aggregate_kernel(const __half* __restrict__ hH,
                                 const float* __restrict__ bias,
                                 const float* __restrict__ als,
                                 const float* __restrict__ ald_arr,
                                 __half* __restrict__ out_h) {
    int node = (blockIdx.x * blockDim.x + threadIdx.x) >> 5;
    int lane = threadIdx.x & 31;
    if (node >= N_NODES) return;
    int beg = node * SLOT_CAP;
    int deg = g_deg[node];
    float ald = ald_arr[node];

    float el[4];
    int   sl[4];
    float m = -INFINITY;
    #pragma unroll
    for (int k = 0; k < 4; k++) {
        int idx = lane + k * 32;
        if (idx < deg) {
            int s0 = g_srcs[beg + idx];
            sl[k] = s0;
            float e = als[s0] + ald;
            e = (e > 0.f) ? e : NEG_SLOPE * e;
            el[k] = e;
            m = fmaxf(m, e);
        } else { sl[k] = 0; el[k] = -INFINITY; }
    }
    #pragma unroll
    for (int o = 16; o > 0; o >>= 1) m = fmaxf(m, __shfl_xor_sync(0xffffffffu, m, o));
    float wl[4];
    float s = 0.f;
    #pragma unroll
    for (int k = 0; k < 4; k++) {
        float w = (el[k] == -INFINITY) ? 0.f : __expf(el[k] - m);
        wl[k] = w;
        s += w;
    }
    #pragma unroll
    for (int o = 16; o > 0; o >>= 1) s += __shfl_xor_sync(0xffffffffu, s, o);
    float inv = 1.f / (s + EPS_F);

    float4 acc0 = make_float4(0.f, 0.f, 0.f, 0.f);
    float4 acc1 = make_float4(0.f, 0.f, 0.f, 0.f);
    #pragma unroll
    for (int k = 0; k < 4; k++) {
        int base_j = k * 32;
        if (base_j >= deg) break;
        int cnt = min(32, deg - base_j);
        for (int t = 0; t < cnt; t++) {
            float w   = __shfl_sync(0xffffffffu, wl[k], t);
            int   src = __shfl_sync(0xffffffffu, sl[k], t);
            uint4 v = __ldg(reinterpret_cast<const uint4*>(hH + (size_t)src * F) + lane);
            const __half2* hp = reinterpret_cast<const __half2*>(&v);
            float2 f0 = __half22float2(hp[0]);
            float2 f1 = __half22float2(hp[1]);
            float2 f2 = __half22float2(hp[2]);
            float2 f3 = __half22float2(hp[3]);
            acc0.x = fmaf(w, f0.x, acc0.x); acc0.y = fmaf(w, f0.y, acc0.y);
            acc0.z = fmaf(w, f1.x, acc0.z); acc0.w = fmaf(w, f1.y, acc0.w);
            acc1.x = fmaf(w, f2.x, acc1.x); acc1.y = fmaf(w, f2.y, acc1.y);
            acc1.z = fmaf(w, f3.x, acc1.z); acc1.w = fmaf(w, f3.y, acc1.w);
        }
    }

    size_t base = (size_t)node * F + (size_t)lane * 8;
    const float* bp = bias + lane * 8;
    __half2 oh[4] = {
        __floats2half2_rn(acc0.x * inv + __ldg(bp + 0), acc0.y * inv + __ldg(bp + 1)),
        __floats2half2_rn(acc0.z * inv + __ldg(bp + 2), acc0.w * inv + __ldg(bp + 3)),
        __floats2half2_rn(acc1.x * inv + __ldg(bp + 4), acc1.y * inv + __ldg(bp + 5)),
        __floats2half2_rn(acc1.z * inv + __ldg(bp + 6), acc1.w * inv + __ldg(bp + 7)) };
    *reinterpret_cast<uint4*>(out_h + base) = *reinterpret_cast<uint4*>(oh);
}

// ---------------- eval-edge dot products (fp16 inputs) + state restore ----------------
#define DOT_B ((E_EVAL * 32 + 255) / 256)     // 12500
#define CLEAN_ELEMS (5 * N_NODES + F)
#define CLEAN_B ((CLEAN_ELEMS + 2047) / 2048) // 25
__global__ void dot_kernel(const __half* __restrict__ h,
                           const int* __restrict__ ei,
                           float* __restrict__ out) {
    int b = blockIdx.x;
    if (b >= DOT_B) {
        int base = (b - DOT_B) * 2048 + threadIdx.x;
        #pragma unroll
        for (int q = 0; q < 8; q++) {
            int i = base + q * 256;
            if (i < N_NODES) g_deg[i] = 0;
            else if (i < 2 * N_NODES) g_als1[i - N_NODES] = 0.f;
            else if (i < 3 * N_NODES) g_ald1[i - 2 * N_NODES] = 0.f;
            else if (i < 4 * N_NODES) g_als2[i - 3 * N_NODES] = 0.f;
            else if (i < 5 * N_NODES) g_ald2[i - 4 * N_NODES] = 0.f;
            else if (i < 5 * N_NODES + F) g_bc[i - 5 * N_NODES] = 0.f;
        }
        return;
    }
    int eid = (b * blockDim.x + threadIdx.x) >> 5;
    int lane = threadIdx.x & 31;
    if (eid >= E_EVAL) return;
    int a = ei[eid];
    int bb = ei[E_EVAL + eid];
    uint4 va = __ldg(reinterpret_cast<const uint4*>(h + (size_t)a * F) + lane);
    uint4 vb = __ldg(reinterpret_cast<const uint4*>(h + (size_t)bb * F) + lane);
    const __half2* pa = reinterpret_cast<const __half2*>(&va);
    const __half2* pb = reinterpret_cast<const __half2*>(&vb);
    float s = 0.f;
    #pragma unroll
    for (int k = 0; k < 4; k++) {
        float2 fa = __half22float2(pa[k]);
        float2 fb = __half22float2(pb[k]);
        s = fmaf(fa.x, fb.x, s);
        s = fmaf(fa.y, fb.y, s);
    }
    #pragma unroll
    for (int o = 16; o > 0; o >>= 1) s += __shfl_xor_sync(0xffffffffu, s, o);
    if (lane == 0) out[eid] = s;
}

// ---------------- launch ----------------
extern "C" void kernel_launch(void* const* d_in, const int* in_sizes, int n_in,
                              void* d_out, int out_size) {
    const float* x       = (const float*)d_in[0];
    const int*   pos_ei  = (const int*)  d_in[1];
    const int*   ev_ei   = (const int*)  d_in[2];
    const float* Win_W   = (const float*)d_in[3];
    const float* Win_b   = (const float*)d_in[4];
    const float* W1      = (const float*)d_in[5];
    const float* a1_src  = (const float*)d_in[6];
    const float* a1_dst  = (const float*)d_in[7];
    const float* b1      = (const float*)d_in[8];
    const float* W2      = (const float*)d_in[9];
    const float* a2_src  = (const float*)d_in[10];
    const float* a2_dst  = (const float*)d_in[11];
    const float* b2      = (const float*)d_in[12];
    float* out = (float*)d_out;

    float *pAls1, *pAld1, *pAls2, *pAld2, *pBc;
    __half *pXH, *pH1, *pH, *pHO, *pWc, *pW2;
    __nv_bfloat16 *pXh, *pXl, *pW1h, *pW1l;
    cudaGetSymbolAddress((void**)&pXH, g_xH);
    cudaGetSymbolAddress((void**)&pH1, g_h1H);
    cudaGetSymbolAddress((void**)&pH, g_bufH);
    cudaGetSymbolAddress((void**)&pHO, g_hOut);
    cudaGetSymbolAddress((void**)&pAls1, g_als1);
    cudaGetSymbolAddress((void**)&pAld1, g_ald1);
    cudaGetSymbolAddress((void**)&pAls2, g_als2);
    cudaGetSymbolAddress((void**)&pAld2, g_ald2);
    cudaGetSymbolAddress((void**)&pBc, g_bc);
    cudaGetSymbolAddress((void**)&pXh, g_Xh);
    cudaGetSymbolAddress((void**)&pXl, g_Xl);
    cudaGetSymbolAddress((void**)&pW1h, g_W1h);
    cudaGetSymbolAddress((void**)&pW1l, g_W1l);
    cudaGetSymbolAddress((void**)&pWc, g_WcH);
    cudaGetSymbolAddress((void**)&pW2, g_W2H);

    cudaFuncSetAttribute(gemm_fold_kernel,
                         cudaFuncAttributeMaxDynamicSharedMemorySize, SMEM_FOLD);
    cudaFuncSetAttribute(gemm16_kernel,
                         cudaFuncAttributeMaxDynamicSharedMemorySize, SMEM_G16);

    const dim3 ggrid(2, (N_NODES + 63) / 64);
    const dim3 fgrid(2, F / 64);
    const int warps_blocks_n = (N_NODES * 32 + 255) / 256;

    // fused: scatter + x->fp16 + weight splits/converts + fold_bias
    work_kernel<<<WORK_B, 256>>>(pos_ei, x, Win_W, W1, W2, Win_b);

    // fold: Wc = Win_W @ W1 (bf16 3-term) -> fp16 [n][k]
    gemm_fold_kernel<<<fgrid, 256, SMEM_FOLD>>>(pXh, pXl, pW1h, pW1l, F);

    // gemm1: hW1 = x @ Wc + bc -> fp16 + fused al1
    gemm16_kernel<<<ggrid, 256, SMEM_G16>>>(
        pXH, pWc, pBc, a1_src, a1_dst, pAls1, pAld1, pH, N_NODES);
    aggregate_kernel<<<warps_blocks_n, 256>>>(pH, b1, pAls1, pAld1, pH1);

    // gemm2: hW2 = h1 @ W2 -> fp16 + fused al2
    gemm16_kernel<<<ggrid, 256, SMEM_G16>>>(
        pH1, pW2, nullptr, a2_src, a2_dst, pAls2, pAld2, pH, N_NODES);
    aggregate_kernel<<<warps_blocks_n, 256>>>(pH, b2, pAls2, pAld2, pHO);

    // eval logits + state restore
    dot_kernel<<<DOT_B + CLEAN_B, 256>>>(pHO, ev_ei, out);
}